// round 1
// baseline (speedup 1.0000x reference)
#include <cuda_runtime.h>

// Problem constants: B=2, M=N=2048, C=D=1024, H=16, hd=64
#define RTOT 4096          // B*N rows
#define DIM  1024
#define NHEAD 16
#define HD   64
#define SEQ  2048

// Scratch buffers (device globals -- no allocation allowed in kernel_launch)
__device__ float g_K[2*2048*1024];
__device__ float g_Q[2*2048*1024];
__device__ float g_V[2*2048*1024];
__device__ float g_Y[2*2048*1024];

// ---------------------------------------------------------------------------
// GEMM: Y[R, Dout] = X[R, Cin] @ W[Cin, Dout] + bias
// 128x128 block tile, BK=16, 256 threads, 8x8 register micro-tile.
// ---------------------------------------------------------------------------
__global__ __launch_bounds__(256, 2)
void gemm_bias_kernel(const float* __restrict__ X, const float* __restrict__ W,
                      const float* __restrict__ bias, float* __restrict__ Y,
                      int R, int Cin, int Dout)
{
    __shared__ float As[16][132];   // A^T tile: [k][m], padded (132*4B = 16B-aligned rows)
    __shared__ float Bs[16][128];   // B tile:   [k][n]

    const int t  = threadIdx.x;
    const int tx = t & 15;
    const int ty = t >> 4;
    const int row0 = blockIdx.y * 128;
    const int col0 = blockIdx.x * 128;

    float acc[8][8];
#pragma unroll
    for (int i = 0; i < 8; i++)
#pragma unroll
        for (int j = 0; j < 8; j++) acc[i][j] = 0.f;

    for (int kt = 0; kt < Cin; kt += 16) {
        // load A tile (128 rows x 16 cols), store transposed
#pragma unroll
        for (int it = 0; it < 2; it++) {
            int f  = t + it * 256;          // 0..511
            int r  = f >> 2;                // 0..127
            int c4 = (f & 3) << 2;          // 0,4,8,12
            float4 v = *(const float4*)(X + (size_t)(row0 + r) * Cin + kt + c4);
            As[c4 + 0][r] = v.x;
            As[c4 + 1][r] = v.y;
            As[c4 + 2][r] = v.z;
            As[c4 + 3][r] = v.w;
        }
        // load B tile (16 rows x 128 cols)
#pragma unroll
        for (int it = 0; it < 2; it++) {
            int f  = t + it * 256;          // 0..511
            int r  = f >> 5;                // 0..15
            int c4 = (f & 31) << 2;         // 0..124
            *(float4*)(&Bs[r][c4]) =
                *(const float4*)(W + (size_t)(kt + r) * Dout + col0 + c4);
        }
        __syncthreads();

#pragma unroll
        for (int k = 0; k < 16; k++) {
            float a[8], b[8];
            *(float4*)&a[0] = *(float4*)&As[k][ty * 8];
            *(float4*)&a[4] = *(float4*)&As[k][ty * 8 + 4];
            *(float4*)&b[0] = *(float4*)&Bs[k][tx * 8];
            *(float4*)&b[4] = *(float4*)&Bs[k][tx * 8 + 4];
#pragma unroll
            for (int i = 0; i < 8; i++)
#pragma unroll
                for (int j = 0; j < 8; j++)
                    acc[i][j] = fmaf(a[i], b[j], acc[i][j]);
        }
        __syncthreads();
    }

#pragma unroll
    for (int i = 0; i < 8; i++) {
        int r = row0 + ty * 8 + i;
#pragma unroll
        for (int j4 = 0; j4 < 8; j4 += 4) {
            int c = col0 + tx * 8 + j4;
            float4 o;
            o.x = acc[i][j4 + 0] + bias[c + 0];
            o.y = acc[i][j4 + 1] + bias[c + 1];
            o.z = acc[i][j4 + 2] + bias[c + 2];
            o.w = acc[i][j4 + 3] + bias[c + 3];
            *(float4*)(Y + (size_t)r * Dout + c) = o;
        }
    }
}

// ---------------------------------------------------------------------------
// Flash attention, fp32. Grid: (SEQ/64, H, B). Block: 256 threads.
// BQ=64 q-rows per block, key tiles of 64, online softmax.
// Thread (ty,tx): q-rows 4*ty..4*ty+3, cols (k or dv) 4*tx..4*tx+3.
// smem: Qts (Q^T [d][q]), KP (K^T [d][k], reused as P [q][k]), Vs [k][dv].
// Exactly 48KB static smem.
// ---------------------------------------------------------------------------
__global__ __launch_bounds__(256)
void attn_kernel(const float* __restrict__ Q, const float* __restrict__ K,
                 const float* __restrict__ V, float* __restrict__ Y)
{
    __shared__ float Qts[64][64];
    __shared__ float KP[64][64];   // Kts then Ps (reused)
    __shared__ float Vs[64][64];

    const int t  = threadIdx.x;
    const int tx = t & 15;
    const int ty = t >> 4;
    const int n0 = blockIdx.x * 64;
    const int h  = blockIdx.y;
    const int b  = blockIdx.z;
    const size_t base = (size_t)b * SEQ * DIM + (size_t)h * HD;
    const float scale = 0.125f;   // 1/sqrt(64)

    // load Q tile transposed: Qts[d][q]
#pragma unroll
    for (int it = 0; it < 4; it++) {
        int f  = t + it * 256;       // 0..1023
        int r  = f >> 4;             // q-row 0..63
        int c4 = (f & 15) << 2;      // d 0..60
        float4 v = *(const float4*)(Q + base + (size_t)(n0 + r) * DIM + c4);
        Qts[c4 + 0][r] = v.x;
        Qts[c4 + 1][r] = v.y;
        Qts[c4 + 2][r] = v.z;
        Qts[c4 + 3][r] = v.w;
    }

    float acc[4][4];
    float mrow[4], lrow[4];
#pragma unroll
    for (int i = 0; i < 4; i++) {
        mrow[i] = -1e30f;
        lrow[i] = 0.f;
#pragma unroll
        for (int j = 0; j < 4; j++) acc[i][j] = 0.f;
    }

    for (int kt = 0; kt < SEQ / 64; kt++) {
        const int m0 = kt * 64;
        __syncthreads();   // previous tile's smem reads complete

        // load K transposed + V direct
#pragma unroll
        for (int it = 0; it < 4; it++) {
            int f  = t + it * 256;
            int r  = f >> 4;
            int c4 = (f & 15) << 2;
            size_t gi = base + (size_t)(m0 + r) * DIM + c4;
            float4 kv = *(const float4*)(K + gi);
            KP[c4 + 0][r] = kv.x;
            KP[c4 + 1][r] = kv.y;
            KP[c4 + 2][r] = kv.z;
            KP[c4 + 3][r] = kv.w;
            *(float4*)&Vs[r][c4] = *(const float4*)(V + gi);
        }
        __syncthreads();

        // S = Q K^T  (raw logits, scaled later)
        float s[4][4];
#pragma unroll
        for (int i = 0; i < 4; i++)
#pragma unroll
            for (int j = 0; j < 4; j++) s[i][j] = 0.f;

#pragma unroll 8
        for (int d = 0; d < 64; d++) {
            float4 qv = *(float4*)&Qts[d][ty * 4];
            float4 kv = *(float4*)&KP[d][tx * 4];
            float qa[4] = {qv.x, qv.y, qv.z, qv.w};
            float ka[4] = {kv.x, kv.y, kv.z, kv.w};
#pragma unroll
            for (int i = 0; i < 4; i++)
#pragma unroll
                for (int j = 0; j < 4; j++)
                    s[i][j] = fmaf(qa[i], ka[j], s[i][j]);
        }

        // online softmax per row (row group = 16 contiguous lanes within warp)
#pragma unroll
        for (int i = 0; i < 4; i++) {
            float rmax = fmaxf(fmaxf(s[i][0], s[i][1]), fmaxf(s[i][2], s[i][3])) * scale;
#pragma unroll
            for (int o = 1; o < 16; o <<= 1)
                rmax = fmaxf(rmax, __shfl_xor_sync(0xffffffffu, rmax, o));
            float newm = fmaxf(mrow[i], rmax);
            float corr = __expf(mrow[i] - newm);
            float psum = 0.f;
#pragma unroll
            for (int j = 0; j < 4; j++) {
                s[i][j] = __expf(fmaf(s[i][j], scale, -newm));
                psum += s[i][j];
            }
#pragma unroll
            for (int o = 1; o < 16; o <<= 1)
                psum += __shfl_xor_sync(0xffffffffu, psum, o);
            lrow[i] = lrow[i] * corr + psum;
            mrow[i] = newm;
#pragma unroll
            for (int j = 0; j < 4; j++) acc[i][j] *= corr;
        }

        __syncthreads();   // everyone done reading KP as K^T
#pragma unroll
        for (int i = 0; i < 4; i++)
            *(float4*)&KP[ty * 4 + i][tx * 4] =
                make_float4(s[i][0], s[i][1], s[i][2], s[i][3]);
        __syncthreads();

        // O += P V
#pragma unroll 4
        for (int k = 0; k < 64; k++) {
            float4 vv = *(float4*)&Vs[k][tx * 4];
            float va[4] = {vv.x, vv.y, vv.z, vv.w};
            float pa[4];
#pragma unroll
            for (int i = 0; i < 4; i++) pa[i] = KP[ty * 4 + i][k];
#pragma unroll
            for (int i = 0; i < 4; i++)
#pragma unroll
                for (int j = 0; j < 4; j++)
                    acc[i][j] = fmaf(pa[i], va[j], acc[i][j]);
        }
    }

    // write y[b, n, h*64 + dv]
#pragma unroll
    for (int i = 0; i < 4; i++) {
        float inv = 1.0f / lrow[i];
        float4 o = make_float4(acc[i][0] * inv, acc[i][1] * inv,
                               acc[i][2] * inv, acc[i][3] * inv);
        *(float4*)(Y + base + (size_t)(n0 + ty * 4 + i) * DIM + tx * 4) = o;
    }
}

// ---------------------------------------------------------------------------
// Inputs (metadata order): kv, q, Wk, bk, Wq, bq, Wv, bv, Wp, bp
// ---------------------------------------------------------------------------
extern "C" void kernel_launch(void* const* d_in, const int* in_sizes, int n_in,
                              void* d_out, int out_size)
{
    const float* kv = (const float*)d_in[0];
    const float* q  = (const float*)d_in[1];
    const float* Wk = (const float*)d_in[2];
    const float* bk = (const float*)d_in[3];
    const float* Wq = (const float*)d_in[4];
    const float* bq = (const float*)d_in[5];
    const float* Wv = (const float*)d_in[6];
    const float* bv = (const float*)d_in[7];
    const float* Wp = (const float*)d_in[8];
    const float* bp = (const float*)d_in[9];
    float* out = (float*)d_out;

    float *pK, *pQ, *pV, *pY;
    cudaGetSymbolAddress((void**)&pK, g_K);
    cudaGetSymbolAddress((void**)&pQ, g_Q);
    cudaGetSymbolAddress((void**)&pV, g_V);
    cudaGetSymbolAddress((void**)&pY, g_Y);

    dim3 gg(DIM / 128, RTOT / 128);   // (8, 32)
    gemm_bias_kernel<<<gg, 256>>>(kv, Wk, bk, pK, RTOT, DIM, DIM);
    gemm_bias_kernel<<<gg, 256>>>(q,  Wq, bq, pQ, RTOT, DIM, DIM);
    gemm_bias_kernel<<<gg, 256>>>(kv, Wv, bv, pV, RTOT, DIM, DIM);

    dim3 ga(SEQ / 64, NHEAD, 2);      // (32, 16, 2)
    attn_kernel<<<ga, 256>>>(pQ, pK, pV, pY);

    gemm_bias_kernel<<<gg, 256>>>(pY, Wp, bp, out, RTOT, DIM, DIM);
}

// round 4
// speedup vs baseline: 2.7395x; 2.7395x over previous
#include <cuda_runtime.h>
#include <cstdint>

// Problem constants: B=2, M=N=2048, C=D=1024, H=16, hd=64
#define RTOT 4096
#define DIM  1024
#define NHEAD 16
#define HD   64
#define SEQ  2048

// Scratch (device globals; no allocation allowed)
__device__ float g_K[2*2048*1024];
__device__ float g_Q[2*2048*1024];
__device__ float g_V[2*2048*1024];
__device__ float g_Y[2*2048*1024];
__device__ float g_Wt[4][1024*1024];   // transposed weights [Dout][Cin]

// ---------------------------------------------------------------------------
// helpers
// ---------------------------------------------------------------------------
__device__ __forceinline__ float tf32r(float x) {
    uint32_t y;
    asm("cvt.rna.tf32.f32 %0, %1;" : "=r"(y) : "f"(x));
    return __uint_as_float(y);
}
__device__ __forceinline__ uint32_t fu(float x) { return __float_as_uint(x); }

// m16n8k8 tf32 mma: D = A(16x8 row) * B(8x8 col) + D
__device__ __forceinline__ void mma8(float* c, const uint32_t* a, const uint32_t* b) {
    asm volatile(
        "mma.sync.aligned.m16n8k8.row.col.f32.tf32.tf32.f32 "
        "{%0,%1,%2,%3}, {%4,%5,%6,%7}, {%8,%9}, {%0,%1,%2,%3};"
        : "+f"(c[0]), "+f"(c[1]), "+f"(c[2]), "+f"(c[3])
        : "r"(a[0]), "r"(a[1]), "r"(a[2]), "r"(a[3]), "r"(b[0]), "r"(b[1]));
}

// ---------------------------------------------------------------------------
// Weight transpose: Wt[n][k] = W[k][n], 1024x1024. grid(32,32), block(32,8)
// ---------------------------------------------------------------------------
__global__ void transpose_kernel(const float* __restrict__ W, float* __restrict__ Wt)
{
    __shared__ float tile[32][33];
    int x = blockIdx.x * 32 + threadIdx.x;
    int y = blockIdx.y * 32 + threadIdx.y;
#pragma unroll
    for (int j = 0; j < 32; j += 8)
        tile[threadIdx.y + j][threadIdx.x] = W[(size_t)(y + j) * 1024 + x];
    __syncthreads();
    x = blockIdx.y * 32 + threadIdx.x;
    y = blockIdx.x * 32 + threadIdx.y;
#pragma unroll
    for (int j = 0; j < 32; j += 8)
        Wt[(size_t)(y + j) * 1024 + x] = tile[threadIdx.x][threadIdx.y + j];
}

// ---------------------------------------------------------------------------
// tf32 mma.sync GEMM: Y[4096,1024] = X @ Wt^T + bias.  Wt is [Dout][Cin].
// 128x128 CTA tile, BK=32, 8 warps (4M x 2N), warp tile 32x64.
// SMEM rows padded to 36 words -> conflict-free fragment LDS.
// ---------------------------------------------------------------------------
#define GSM_BUF 4608            // 128 * 36 floats
__global__ __launch_bounds__(256, 2)
void gemm_mma_kernel(const float* __restrict__ X, const float* __restrict__ Wt,
                     const float* __restrict__ bias, float* __restrict__ Y)
{
    extern __shared__ float sm[];
    float* As = sm;                 // 2 * 4608
    float* Bs = sm + 2 * GSM_BUF;   // 2 * 4608

    const int t  = threadIdx.x;
    const int w  = t >> 5, l = t & 31;
    const int wm = w & 3, wn = w >> 2;
    const int lg = l >> 2, lt = l & 3;
    const int row0 = blockIdx.y * 128;
    const int col0 = blockIdx.x * 128;

    float c[2][8][4];
#pragma unroll
    for (int i = 0; i < 2; i++)
#pragma unroll
        for (int j = 0; j < 8; j++)
#pragma unroll
            for (int r = 0; r < 4; r++) c[i][j][r] = 0.f;

    // full tile: 128 rows x 32 floats = 1024 float4 per operand
    // -> 4 float4 per thread per operand
    float4 xa[4], xb[4];
    auto ldg = [&](int s) {
        const int k0 = s * 32;
#pragma unroll
        for (int i = 0; i < 4; i++) {
            int f = t + i * 256;          // 0..1023
            int r = f >> 3, k4 = f & 7;   // r: 0..127
            xa[i] = *(const float4*)(X  + (size_t)(row0 + r) * DIM + k0 + k4 * 4);
            xb[i] = *(const float4*)(Wt + (size_t)(col0 + r) * DIM + k0 + k4 * 4);
        }
    };
    auto sts = [&](int b) {
        float* A = As + b * GSM_BUF;
        float* B = Bs + b * GSM_BUF;
#pragma unroll
        for (int i = 0; i < 4; i++) {
            int f = t + i * 256;
            int r = f >> 3, k4 = f & 7;
            float4 v = xa[i];
            v.x = tf32r(v.x); v.y = tf32r(v.y); v.z = tf32r(v.z); v.w = tf32r(v.w);
            *(float4*)(A + r * 36 + k4 * 4) = v;
            v = xb[i];
            v.x = tf32r(v.x); v.y = tf32r(v.y); v.z = tf32r(v.z); v.w = tf32r(v.w);
            *(float4*)(B + r * 36 + k4 * 4) = v;
        }
    };

    ldg(0); sts(0); __syncthreads();

    for (int s = 0; s < 32; s++) {
        int b = s & 1;
        if (s + 1 < 32) ldg(s + 1);
        const float* A  = As + b * GSM_BUF;
        const float* Bt = Bs + b * GSM_BUF;
#pragma unroll
        for (int kk = 0; kk < 4; kk++) {
            uint32_t af[2][4], bf[8][2];
#pragma unroll
            for (int i = 0; i < 2; i++) {
                const float* ap = A + (wm * 32 + i * 16 + lg) * 36 + kk * 8 + lt;
                af[i][0] = fu(ap[0]);
                af[i][1] = fu(ap[8 * 36]);
                af[i][2] = fu(ap[4]);
                af[i][3] = fu(ap[8 * 36 + 4]);
            }
#pragma unroll
            for (int j = 0; j < 8; j++) {
                const float* bp = Bt + (wn * 64 + j * 8 + lg) * 36 + kk * 8 + lt;
                bf[j][0] = fu(bp[0]);
                bf[j][1] = fu(bp[4]);
            }
#pragma unroll
            for (int i = 0; i < 2; i++)
#pragma unroll
                for (int j = 0; j < 8; j++)
                    mma8(c[i][j], af[i], bf[j]);
        }
        if (s + 1 < 32) { sts((s + 1) & 1); __syncthreads(); }
    }

    // epilogue: C fragments + bias -> global
#pragma unroll
    for (int i = 0; i < 2; i++) {
        int r0 = row0 + wm * 32 + i * 16 + lg;
#pragma unroll
        for (int j = 0; j < 8; j++) {
            int cc = col0 + wn * 64 + j * 8 + 2 * lt;
            float2 bb = *(const float2*)(bias + cc);
            float2 o0 = { c[i][j][0] + bb.x, c[i][j][1] + bb.y };
            float2 o1 = { c[i][j][2] + bb.x, c[i][j][3] + bb.y };
            *(float2*)(Y + (size_t)r0 * DIM + cc)       = o0;
            *(float2*)(Y + (size_t)(r0 + 8) * DIM + cc) = o1;
        }
    }
}

// ---------------------------------------------------------------------------
// Flash attention on tf32 mma.sync.
// Grid (SEQ/64, H, B), 256 threads (8 warps, 4M x 2N), q-tile 64, k-tile 64.
// SMEM: Qs[64][68], KP[64][68] (K then P), Vs[64][72], m/l/corr[64].
// ---------------------------------------------------------------------------
__global__ __launch_bounds__(256)
void attn_mma_kernel(const float* __restrict__ Q, const float* __restrict__ K,
                     const float* __restrict__ V, float* __restrict__ Y)
{
    extern __shared__ float sm[];
    float* Qs   = sm;               // 64*68 = 4352
    float* KP   = sm + 4352;        // 4352
    float* Vs   = sm + 8704;        // 64*72 = 4608
    float* mrow = sm + 13312;       // 64
    float* lsum = sm + 13376;       // 64
    float* corr = sm + 13440;       // 64

    const int t  = threadIdx.x;
    const int w  = t >> 5, l = t & 31;
    const int wm = w & 3, wn = w >> 2;
    const int lg = l >> 2, lt = l & 3;
    const int n0 = blockIdx.x * 64;
    const size_t base = (size_t)blockIdx.z * SEQ * DIM + (size_t)blockIdx.y * HD;
    const float scale = 0.125f;

    // load Q tile (tf32-rounded)
#pragma unroll
    for (int it = 0; it < 4; it++) {
        int f = t + it * 256;
        int r = f >> 4, c4 = (f & 15) << 2;
        float4 v = *(const float4*)(Q + base + (size_t)(n0 + r) * DIM + c4);
        v.x = tf32r(v.x); v.y = tf32r(v.y); v.z = tf32r(v.z); v.w = tf32r(v.w);
        *(float4*)(Qs + r * 68 + c4) = v;
    }
    if (t < 64) { mrow[t] = -1e30f; lsum[t] = 0.f; }

    float o[4][4];
#pragma unroll
    for (int j = 0; j < 4; j++)
#pragma unroll
        for (int r = 0; r < 4; r++) o[j][r] = 0.f;

    for (int kt = 0; kt < SEQ / 64; kt++) {
        __syncthreads();   // prev-iter P/V reads done
        // load K (into KP) and V, tf32-rounded
#pragma unroll
        for (int it = 0; it < 4; it++) {
            int f = t + it * 256;
            int r = f >> 4, c4 = (f & 15) << 2;
            size_t gi = base + (size_t)(kt * 64 + r) * DIM + c4;
            float4 kv = *(const float4*)(K + gi);
            kv.x = tf32r(kv.x); kv.y = tf32r(kv.y); kv.z = tf32r(kv.z); kv.w = tf32r(kv.w);
            *(float4*)(KP + r * 68 + c4) = kv;
            float4 vv = *(const float4*)(V + gi);
            vv.x = tf32r(vv.x); vv.y = tf32r(vv.y); vv.z = tf32r(vv.z); vv.w = tf32r(vv.w);
            *(float4*)(Vs + r * 72 + c4) = vv;
        }
        __syncthreads();

        // S = Q K^T : warp computes 16(q) x 32(kk)
        float s4[4][4];
#pragma unroll
        for (int j = 0; j < 4; j++)
#pragma unroll
            for (int r = 0; r < 4; r++) s4[j][r] = 0.f;

#pragma unroll
        for (int kk = 0; kk < 8; kk++) {
            uint32_t af[4];
            const float* ap = Qs + (wm * 16 + lg) * 68 + kk * 8 + lt;
            af[0] = fu(ap[0]);
            af[1] = fu(ap[8 * 68]);
            af[2] = fu(ap[4]);
            af[3] = fu(ap[8 * 68 + 4]);
#pragma unroll
            for (int j = 0; j < 4; j++) {
                const float* bp = KP + (wn * 32 + j * 8 + lg) * 68 + kk * 8 + lt;
                uint32_t bf[2] = { fu(bp[0]), fu(bp[4]) };
                mma8(s4[j], af, bf);
            }
        }
        __syncthreads();   // all warps done reading K from KP

        // store S fragments into KP (as [q][kk_local])
#pragma unroll
        for (int j = 0; j < 4; j++) {
            int cc = wn * 32 + j * 8 + 2 * lt;
            *(float2*)(KP + (wm * 16 + lg) * 68 + cc)     = make_float2(s4[j][0], s4[j][1]);
            *(float2*)(KP + (wm * 16 + 8 + lg) * 68 + cc) = make_float2(s4[j][2], s4[j][3]);
        }
        __syncthreads();

        // softmax: 4 lanes per q-row, 16 cols each
        {
            int row = t >> 2, sub = t & 3;
            float* rp = KP + row * 68 + sub * 16;
            float4 v0 = *(float4*)(rp + 0);
            float4 v1 = *(float4*)(rp + 4);
            float4 v2 = *(float4*)(rp + 8);
            float4 v3 = *(float4*)(rp + 12);
            float vmax = fmaxf(fmaxf(fmaxf(v0.x, v0.y), fmaxf(v0.z, v0.w)),
                               fmaxf(fmaxf(v1.x, v1.y), fmaxf(v1.z, v1.w)));
            vmax = fmaxf(vmax, fmaxf(fmaxf(fmaxf(v2.x, v2.y), fmaxf(v2.z, v2.w)),
                                     fmaxf(fmaxf(v3.x, v3.y), fmaxf(v3.z, v3.w))));
            vmax = fmaxf(vmax, __shfl_xor_sync(0xffffffffu, vmax, 1));
            vmax = fmaxf(vmax, __shfl_xor_sync(0xffffffffu, vmax, 2));
            float mprev = mrow[row];
            float newm  = fmaxf(mprev, vmax * scale);
            float cv    = __expf(mprev - newm);
            float ps = 0.f;
            float4 e;
#define EXP4(V) \
            e.x = __expf(fmaf((V).x, scale, -newm)); \
            e.y = __expf(fmaf((V).y, scale, -newm)); \
            e.z = __expf(fmaf((V).z, scale, -newm)); \
            e.w = __expf(fmaf((V).w, scale, -newm)); \
            ps += (e.x + e.y) + (e.z + e.w); \
            e.x = tf32r(e.x); e.y = tf32r(e.y); e.z = tf32r(e.z); e.w = tf32r(e.w);
            EXP4(v0); *(float4*)(rp + 0)  = e;
            EXP4(v1); *(float4*)(rp + 4)  = e;
            EXP4(v2); *(float4*)(rp + 8)  = e;
            EXP4(v3); *(float4*)(rp + 12) = e;
#undef EXP4
            ps += __shfl_xor_sync(0xffffffffu, ps, 1);
            ps += __shfl_xor_sync(0xffffffffu, ps, 2);
            if (sub == 0) {
                mrow[row] = newm;
                lsum[row] = lsum[row] * cv + ps;
                corr[row] = cv;
            }
        }
        __syncthreads();

        // rescale O, then O += P V
        {
            float c0 = corr[wm * 16 + lg];
            float c1 = corr[wm * 16 + 8 + lg];
#pragma unroll
            for (int j = 0; j < 4; j++) {
                o[j][0] *= c0; o[j][1] *= c0;
                o[j][2] *= c1; o[j][3] *= c1;
            }
        }
#pragma unroll
        for (int kk = 0; kk < 8; kk++) {
            uint32_t af[4];
            const float* ap = KP + (wm * 16 + lg) * 68 + kk * 8 + lt;
            af[0] = fu(ap[0]);
            af[1] = fu(ap[8 * 68]);
            af[2] = fu(ap[4]);
            af[3] = fu(ap[8 * 68 + 4]);
#pragma unroll
            for (int j = 0; j < 4; j++) {
                const float* bp = Vs + (kk * 8 + lt) * 72 + wn * 32 + j * 8 + lg;
                uint32_t bf[2] = { fu(bp[0]), fu(bp[4 * 72]) };
                mma8(o[j], af, bf);
            }
        }
    }

    // final: divide by lsum, write out
    {
        float i0 = 1.0f / lsum[wm * 16 + lg];
        float i1 = 1.0f / lsum[wm * 16 + 8 + lg];
        int r0 = n0 + wm * 16 + lg;
#pragma unroll
        for (int j = 0; j < 4; j++) {
            int cc = wn * 32 + j * 8 + 2 * lt;
            *(float2*)(Y + base + (size_t)r0 * DIM + cc) =
                make_float2(o[j][0] * i0, o[j][1] * i0);
            *(float2*)(Y + base + (size_t)(r0 + 8) * DIM + cc) =
                make_float2(o[j][2] * i1, o[j][3] * i1);
        }
    }
}

// ---------------------------------------------------------------------------
// Inputs: kv, q, Wk, bk, Wq, bq, Wv, bv, Wp, bp
// ---------------------------------------------------------------------------
extern "C" void kernel_launch(void* const* d_in, const int* in_sizes, int n_in,
                              void* d_out, int out_size)
{
    const float* kv = (const float*)d_in[0];
    const float* q  = (const float*)d_in[1];
    const float* Wk = (const float*)d_in[2];
    const float* bk = (const float*)d_in[3];
    const float* Wq = (const float*)d_in[4];
    const float* bq = (const float*)d_in[5];
    const float* Wv = (const float*)d_in[6];
    const float* bv = (const float*)d_in[7];
    const float* Wp = (const float*)d_in[8];
    const float* bp = (const float*)d_in[9];
    float* out = (float*)d_out;

    float *pK, *pQ, *pV, *pY, *pWt;
    cudaGetSymbolAddress((void**)&pK, g_K);
    cudaGetSymbolAddress((void**)&pQ, g_Q);
    cudaGetSymbolAddress((void**)&pV, g_V);
    cudaGetSymbolAddress((void**)&pY, g_Y);
    cudaGetSymbolAddress((void**)&pWt, g_Wt);
    float* Wtk = pWt + 0 * 1024 * 1024;
    float* Wtq = pWt + 1 * 1024 * 1024;
    float* Wtv = pWt + 2 * 1024 * 1024;
    float* Wtp = pWt + 3 * 1024 * 1024;

    const int GEMM_SMEM = 4 * GSM_BUF * 4;   // 73728 B
    const int ATTN_SMEM = 13504 * 4;         // 54016 B
    cudaFuncSetAttribute((const void*)gemm_mma_kernel,
                         cudaFuncAttributeMaxDynamicSharedMemorySize, GEMM_SMEM);
    cudaFuncSetAttribute((const void*)attn_mma_kernel,
                         cudaFuncAttributeMaxDynamicSharedMemorySize, ATTN_SMEM);

    dim3 tb(32, 8), tg(32, 32);
    transpose_kernel<<<tg, tb>>>(Wk, Wtk);
    transpose_kernel<<<tg, tb>>>(Wq, Wtq);
    transpose_kernel<<<tg, tb>>>(Wv, Wtv);
    transpose_kernel<<<tg, tb>>>(Wp, Wtp);

    dim3 gg(DIM / 128, RTOT / 128);   // (8, 32)
    gemm_mma_kernel<<<gg, 256, GEMM_SMEM>>>(kv, Wtk, bk, pK);
    gemm_mma_kernel<<<gg, 256, GEMM_SMEM>>>(q,  Wtq, bq, pQ);
    gemm_mma_kernel<<<gg, 256, GEMM_SMEM>>>(kv, Wtv, bv, pV);

    dim3 ga(SEQ / 64, NHEAD, 2);      // (32, 16, 2)
    attn_mma_kernel<<<ga, 256, ATTN_SMEM>>>(pQ, pK, pV, pY);

    gemm_mma_kernel<<<gg, 256, GEMM_SMEM>>>(pY, Wtp, bp, out);
}

// round 5
// speedup vs baseline: 2.9754x; 1.0861x over previous
#include <cuda_runtime.h>
#include <cstdint>

// Problem constants: B=2, M=N=2048, C=D=1024, H=16, hd=64
#define RTOT 4096
#define DIM  1024
#define NHEAD 16
#define HD   64
#define SEQ  2048

// Scratch (device globals; no allocation allowed)
__device__ float g_K[2*2048*1024];
__device__ float g_Q[2*2048*1024];
__device__ float g_V[2*2048*1024];
__device__ float g_Y[2*2048*1024];
__device__ float g_Wt[4][1024*1024];   // transposed weights [Dout][Cin]

// ---------------------------------------------------------------------------
// helpers
// ---------------------------------------------------------------------------
__device__ __forceinline__ float tf32r(float x) {
    uint32_t y;
    asm("cvt.rna.tf32.f32 %0, %1;" : "=r"(y) : "f"(x));
    return __uint_as_float(y);
}
__device__ __forceinline__ uint32_t fu(float x) { return __float_as_uint(x); }
__device__ __forceinline__ uint32_t cvta_s(const void* p) {
    return (uint32_t)__cvta_generic_to_shared(p);
}

#define CP16(dst, src) \
    asm volatile("cp.async.cg.shared.global [%0], [%1], 16;" :: "r"(dst), "l"(src))
#define CPCOMMIT() asm volatile("cp.async.commit_group;")
#define CPWAIT(n)  asm volatile("cp.async.wait_group %0;" :: "n"(n))

#define LDSM4(r0, r1, r2, r3, addr) \
    asm volatile("ldmatrix.sync.aligned.m8n8.x4.shared.b16 {%0,%1,%2,%3}, [%4];" \
        : "=r"(r0), "=r"(r1), "=r"(r2), "=r"(r3) : "r"(addr))

#define CVTT(r) asm volatile("cvt.rna.tf32.f32 %0, %0;" : "+r"(r))

// m16n8k8 tf32 mma: D = A(16x8 row) * B(8x8 col) + D
__device__ __forceinline__ void mma8(float* c, const uint32_t* a, const uint32_t* b) {
    asm volatile(
        "mma.sync.aligned.m16n8k8.row.col.f32.tf32.tf32.f32 "
        "{%0,%1,%2,%3}, {%4,%5,%6,%7}, {%8,%9}, {%0,%1,%2,%3};"
        : "+f"(c[0]), "+f"(c[1]), "+f"(c[2]), "+f"(c[3])
        : "r"(a[0]), "r"(a[1]), "r"(a[2]), "r"(a[3]), "r"(b[0]), "r"(b[1]));
}

// ---------------------------------------------------------------------------
// Fused weight transpose: Wt[z][n][k] = W_z[k][n], 1024x1024 each.
// grid (32, 32, 4), block (32, 8)
// ---------------------------------------------------------------------------
__global__ void transpose4_kernel(const float* __restrict__ W0,
                                  const float* __restrict__ W1,
                                  const float* __restrict__ W2,
                                  const float* __restrict__ W3,
                                  float* __restrict__ WtAll)
{
    __shared__ float tile[32][33];
    const float* W = (blockIdx.z == 0) ? W0 : (blockIdx.z == 1) ? W1 :
                     (blockIdx.z == 2) ? W2 : W3;
    float* Wt = WtAll + (size_t)blockIdx.z * 1024 * 1024;
    int x = blockIdx.x * 32 + threadIdx.x;
    int y = blockIdx.y * 32 + threadIdx.y;
#pragma unroll
    for (int j = 0; j < 32; j += 8)
        tile[threadIdx.y + j][threadIdx.x] = W[(size_t)(y + j) * 1024 + x];
    __syncthreads();
    x = blockIdx.y * 32 + threadIdx.x;
    y = blockIdx.x * 32 + threadIdx.y;
#pragma unroll
    for (int j = 0; j < 32; j += 8)
        Wt[(size_t)(y + j) * 1024 + x] = tile[threadIdx.x][threadIdx.y + j];
}

// ---------------------------------------------------------------------------
// tf32 mma.sync GEMM: Y[4096,1024] = X @ Wt^T + bias.  Wt is [Dout][Cin].
// 128x128 CTA tile, BK=32, 8 warps (4M x 2N), warp tile 32x64.
// cp.async double-buffer, ldmatrix fragments, cvt.rna on fragments.
// SMEM rows stride 36 words (144B == 16 mod 128 -> conflict-free ldmatrix).
// ---------------------------------------------------------------------------
#define GSM_BUF 4608            // 128 * 36 floats
template<bool ROUND_OUT>
__global__ __launch_bounds__(256)
void gemm_mma_kernel(const float* __restrict__ X, const float* __restrict__ Wt,
                     const float* __restrict__ bias, float* __restrict__ Y)
{
    extern __shared__ float sm[];
    float* As = sm;                 // 2 * 4608
    float* Bs = sm + 2 * GSM_BUF;   // 2 * 4608
    const uint32_t sA = cvta_s(As), sB = cvta_s(Bs);

    const int t  = threadIdx.x;
    const int w  = t >> 5, l = t & 31;
    const int wm = w & 3, wn = w >> 2;
    const int row0 = blockIdx.y * 128;
    const int col0 = blockIdx.x * 128;

    // ldmatrix per-lane address components
    const int lrow = l & 15;                 // A/P-style frag rows
    const int lcA  = (l >> 4) * 4;           // A col half
    const int lrB  = (l & 7) + (l >> 4) * 8; // B frag rows (j-pair)
    const int lcB  = ((l >> 3) & 1) * 4;     // B col half

    float c[2][8][4];
#pragma unroll
    for (int i = 0; i < 2; i++)
#pragma unroll
        for (int j = 0; j < 8; j++)
#pragma unroll
            for (int r = 0; r < 4; r++) c[i][j][r] = 0.f;

    auto issue = [&](int s) {
        const int k0 = s * 32;
        const uint32_t dA = sA + (uint32_t)((s & 1) * GSM_BUF * 4);
        const uint32_t dB = sB + (uint32_t)((s & 1) * GSM_BUF * 4);
#pragma unroll
        for (int i = 0; i < 4; i++) {
            int f = t + i * 256;            // 0..1023
            int r = f >> 3, k4 = (f & 7) * 4;
            CP16(dA + (uint32_t)((r * 36 + k4) * 4),
                 X + (size_t)(row0 + r) * DIM + k0 + k4);
            CP16(dB + (uint32_t)((r * 36 + k4) * 4),
                 Wt + (size_t)(col0 + r) * DIM + k0 + k4);
        }
        CPCOMMIT();
    };

    issue(0);
    for (int s = 0; s < 32; s++) {
        if (s < 31) { issue(s + 1); CPWAIT(1); }
        else        { CPWAIT(0); }
        __syncthreads();

        const uint32_t bA = sA + (uint32_t)((s & 1) * GSM_BUF * 4);
        const uint32_t bB = sB + (uint32_t)((s & 1) * GSM_BUF * 4);
        const uint32_t a0a = bA + (uint32_t)(((wm * 32 + lrow) * 36 + lcA) * 4);
        const uint32_t b0a = bB + (uint32_t)(((wn * 64 + lrB) * 36 + lcB) * 4);

#pragma unroll
        for (int kk = 0; kk < 4; kk++) {
            uint32_t af[2][4], bf[8][2];
#pragma unroll
            for (int i = 0; i < 2; i++) {
                LDSM4(af[i][0], af[i][1], af[i][2], af[i][3],
                      a0a + (uint32_t)(i * 16 * 36 * 4 + kk * 32));
                CVTT(af[i][0]); CVTT(af[i][1]); CVTT(af[i][2]); CVTT(af[i][3]);
            }
#pragma unroll
            for (int jp = 0; jp < 4; jp++) {
                uint32_t q0, q1, q2, q3;
                LDSM4(q0, q1, q2, q3,
                      b0a + (uint32_t)(jp * 16 * 36 * 4 + kk * 32));
                CVTT(q0); CVTT(q1); CVTT(q2); CVTT(q3);
                bf[2*jp][0] = q0; bf[2*jp][1] = q1;
                bf[2*jp+1][0] = q2; bf[2*jp+1][1] = q3;
            }
#pragma unroll
            for (int i = 0; i < 2; i++)
#pragma unroll
                for (int j = 0; j < 8; j++)
                    mma8(c[i][j], af[i], bf[j]);
        }
        __syncthreads();
    }

    // epilogue: C fragments + bias -> global (optionally tf32-rounded)
    const int lg = l >> 2, lt = l & 3;
#pragma unroll
    for (int i = 0; i < 2; i++) {
        int r0 = row0 + wm * 32 + i * 16 + lg;
#pragma unroll
        for (int j = 0; j < 8; j++) {
            int cc = col0 + wn * 64 + j * 8 + 2 * lt;
            float2 bb = *(const float2*)(bias + cc);
            float2 o0 = { c[i][j][0] + bb.x, c[i][j][1] + bb.y };
            float2 o1 = { c[i][j][2] + bb.x, c[i][j][3] + bb.y };
            if (ROUND_OUT) {
                o0.x = tf32r(o0.x); o0.y = tf32r(o0.y);
                o1.x = tf32r(o1.x); o1.y = tf32r(o1.y);
            }
            *(float2*)(Y + (size_t)r0 * DIM + cc)       = o0;
            *(float2*)(Y + (size_t)(r0 + 8) * DIM + cc) = o1;
        }
    }
}

// ---------------------------------------------------------------------------
// Flash attention on tf32 mma.sync (inputs pre-rounded to tf32 by projections).
// Grid (SEQ/64, H, B), 256 threads (8 warps, 4M x 2N), q-tile 64, k-tile 64.
// cp.async tile loads; ldmatrix for Q/K/P fragments; scalar LDS for V (layout).
// ---------------------------------------------------------------------------
__global__ __launch_bounds__(256)
void attn_mma_kernel(const float* __restrict__ Q, const float* __restrict__ K,
                     const float* __restrict__ V, float* __restrict__ Y)
{
    extern __shared__ float sm[];
    float* Qs   = sm;               // 64*68 = 4352
    float* KP   = sm + 4352;        // 4352 (K tile, then P)
    float* Vs   = sm + 8704;        // 64*72 = 4608
    float* mrow = sm + 13312;       // 64
    float* lsum = sm + 13376;       // 64
    float* corr = sm + 13440;       // 64
    const uint32_t sQ = cvta_s(Qs), sKP = cvta_s(KP), sV = cvta_s(Vs);

    const int t  = threadIdx.x;
    const int w  = t >> 5, l = t & 31;
    const int wm = w & 3, wn = w >> 2;
    const int lg = l >> 2, lt = l & 3;
    const int lrow = l & 15;
    const int lcA  = (l >> 4) * 4;
    const int lrB  = (l & 7) + (l >> 4) * 8;
    const int lcB  = ((l >> 3) & 1) * 4;
    const int n0 = blockIdx.x * 64;
    const size_t base = (size_t)blockIdx.z * SEQ * DIM + (size_t)blockIdx.y * HD;
    const float scale = 0.125f;

    // Q tile via cp.async (values already tf32-rounded by projection epilogue)
#pragma unroll
    for (int it = 0; it < 4; it++) {
        int f = t + it * 256;
        int r = f >> 4, c4 = (f & 15) * 4;
        CP16(sQ + (uint32_t)((r * 68 + c4) * 4),
             Q + base + (size_t)(n0 + r) * DIM + c4);
    }
    CPCOMMIT();
    if (t < 64) { mrow[t] = -1e30f; lsum[t] = 0.f; }

    float o[4][4];
#pragma unroll
    for (int j = 0; j < 4; j++)
#pragma unroll
        for (int r = 0; r < 4; r++) o[j][r] = 0.f;

    for (int kt = 0; kt < SEQ / 64; kt++) {
        __syncthreads();   // prev-iter P/V/Q reads done
        // load K (into KP) and V tiles
#pragma unroll
        for (int it = 0; it < 4; it++) {
            int f = t + it * 256;
            int r = f >> 4, c4 = (f & 15) * 4;
            size_t gi = base + (size_t)(kt * 64 + r) * DIM + c4;
            CP16(sKP + (uint32_t)((r * 68 + c4) * 4), K + gi);
            CP16(sV  + (uint32_t)((r * 72 + c4) * 4), V + gi);
        }
        CPCOMMIT(); CPWAIT(0);
        __syncthreads();

        // S = Q K^T : warp computes 16(q) x 32(k)
        float s4[4][4];
#pragma unroll
        for (int j = 0; j < 4; j++)
#pragma unroll
            for (int r = 0; r < 4; r++) s4[j][r] = 0.f;

        const uint32_t qb = sQ  + (uint32_t)(((wm * 16 + lrow) * 68 + lcA) * 4);
        const uint32_t kb = sKP + (uint32_t)(((wn * 32 + lrB) * 68 + lcB) * 4);
#pragma unroll
        for (int kk = 0; kk < 8; kk++) {
            uint32_t af[4];
            LDSM4(af[0], af[1], af[2], af[3], qb + (uint32_t)(kk * 32));
#pragma unroll
            for (int jp = 0; jp < 2; jp++) {
                uint32_t q0, q1, q2, q3;
                LDSM4(q0, q1, q2, q3,
                      kb + (uint32_t)(jp * 16 * 68 * 4 + kk * 32));
                uint32_t bf0[2] = { q0, q1 }, bf1[2] = { q2, q3 };
                mma8(s4[2*jp],   af, bf0);
                mma8(s4[2*jp+1], af, bf1);
            }
        }
        __syncthreads();   // all warps done reading K from KP

        // store S fragments into KP (as [q][k_local])
#pragma unroll
        for (int j = 0; j < 4; j++) {
            int cc = wn * 32 + j * 8 + 2 * lt;
            *(float2*)(KP + (wm * 16 + lg) * 68 + cc)     = make_float2(s4[j][0], s4[j][1]);
            *(float2*)(KP + (wm * 16 + 8 + lg) * 68 + cc) = make_float2(s4[j][2], s4[j][3]);
        }
        __syncthreads();

        // softmax: 4 lanes per q-row, 16 cols each
        {
            int row = t >> 2, sub = t & 3;
            float* rp = KP + row * 68 + sub * 16;
            float4 v0 = *(float4*)(rp + 0);
            float4 v1 = *(float4*)(rp + 4);
            float4 v2 = *(float4*)(rp + 8);
            float4 v3 = *(float4*)(rp + 12);
            float vmax = fmaxf(fmaxf(fmaxf(v0.x, v0.y), fmaxf(v0.z, v0.w)),
                               fmaxf(fmaxf(v1.x, v1.y), fmaxf(v1.z, v1.w)));
            vmax = fmaxf(vmax, fmaxf(fmaxf(fmaxf(v2.x, v2.y), fmaxf(v2.z, v2.w)),
                                     fmaxf(fmaxf(v3.x, v3.y), fmaxf(v3.z, v3.w))));
            vmax = fmaxf(vmax, __shfl_xor_sync(0xffffffffu, vmax, 1));
            vmax = fmaxf(vmax, __shfl_xor_sync(0xffffffffu, vmax, 2));
            float mprev = mrow[row];
            float newm  = fmaxf(mprev, vmax * scale);
            float cv    = __expf(mprev - newm);
            float ps = 0.f;
            float4 e;
#define EXP4(V) \
            e.x = __expf(fmaf((V).x, scale, -newm)); \
            e.y = __expf(fmaf((V).y, scale, -newm)); \
            e.z = __expf(fmaf((V).z, scale, -newm)); \
            e.w = __expf(fmaf((V).w, scale, -newm)); \
            ps += (e.x + e.y) + (e.z + e.w); \
            e.x = tf32r(e.x); e.y = tf32r(e.y); e.z = tf32r(e.z); e.w = tf32r(e.w);
            EXP4(v0); *(float4*)(rp + 0)  = e;
            EXP4(v1); *(float4*)(rp + 4)  = e;
            EXP4(v2); *(float4*)(rp + 8)  = e;
            EXP4(v3); *(float4*)(rp + 12) = e;
#undef EXP4
            ps += __shfl_xor_sync(0xffffffffu, ps, 1);
            ps += __shfl_xor_sync(0xffffffffu, ps, 2);
            if (sub == 0) {
                mrow[row] = newm;
                lsum[row] = lsum[row] * cv + ps;
                corr[row] = cv;
            }
        }
        __syncthreads();

        // rescale O, then O += P V
        {
            float c0 = corr[wm * 16 + lg];
            float c1 = corr[wm * 16 + 8 + lg];
#pragma unroll
            for (int j = 0; j < 4; j++) {
                o[j][0] *= c0; o[j][1] *= c0;
                o[j][2] *= c1; o[j][3] *= c1;
            }
        }
        const uint32_t pb = sKP + (uint32_t)(((wm * 16 + lrow) * 68 + lcA) * 4);
#pragma unroll
        for (int kk = 0; kk < 8; kk++) {
            uint32_t af[4];
            LDSM4(af[0], af[1], af[2], af[3], pb + (uint32_t)(kk * 32));
#pragma unroll
            for (int j = 0; j < 4; j++) {
                const float* bp = Vs + (kk * 8 + lt) * 72 + wn * 32 + j * 8 + lg;
                uint32_t bf[2] = { fu(bp[0]), fu(bp[4 * 72]) };
                mma8(o[j], af, bf);
            }
        }
    }

    // final: divide by lsum, write out
    {
        float i0 = 1.0f / lsum[wm * 16 + lg];
        float i1 = 1.0f / lsum[wm * 16 + 8 + lg];
        int r0 = n0 + wm * 16 + lg;
#pragma unroll
        for (int j = 0; j < 4; j++) {
            int cc = wn * 32 + j * 8 + 2 * lt;
            *(float2*)(Y + base + (size_t)r0 * DIM + cc) =
                make_float2(o[j][0] * i0, o[j][1] * i0);
            *(float2*)(Y + base + (size_t)(r0 + 8) * DIM + cc) =
                make_float2(o[j][2] * i1, o[j][3] * i1);
        }
    }
}

// ---------------------------------------------------------------------------
// Inputs: kv, q, Wk, bk, Wq, bq, Wv, bv, Wp, bp
// ---------------------------------------------------------------------------
extern "C" void kernel_launch(void* const* d_in, const int* in_sizes, int n_in,
                              void* d_out, int out_size)
{
    const float* kv = (const float*)d_in[0];
    const float* q  = (const float*)d_in[1];
    const float* Wk = (const float*)d_in[2];
    const float* bk = (const float*)d_in[3];
    const float* Wq = (const float*)d_in[4];
    const float* bq = (const float*)d_in[5];
    const float* Wv = (const float*)d_in[6];
    const float* bv = (const float*)d_in[7];
    const float* Wp = (const float*)d_in[8];
    const float* bp = (const float*)d_in[9];
    float* out = (float*)d_out;

    float *pK, *pQ, *pV, *pY, *pWt;
    cudaGetSymbolAddress((void**)&pK, g_K);
    cudaGetSymbolAddress((void**)&pQ, g_Q);
    cudaGetSymbolAddress((void**)&pV, g_V);
    cudaGetSymbolAddress((void**)&pY, g_Y);
    cudaGetSymbolAddress((void**)&pWt, g_Wt);
    float* Wtk = pWt + 0 * 1024 * 1024;
    float* Wtq = pWt + 1 * 1024 * 1024;
    float* Wtv = pWt + 2 * 1024 * 1024;
    float* Wtp = pWt + 3 * 1024 * 1024;

    const int GEMM_SMEM = 4 * GSM_BUF * 4;   // 73728 B
    const int ATTN_SMEM = 13504 * 4;         // 54016 B
    cudaFuncSetAttribute((const void*)gemm_mma_kernel<true>,
                         cudaFuncAttributeMaxDynamicSharedMemorySize, GEMM_SMEM);
    cudaFuncSetAttribute((const void*)gemm_mma_kernel<false>,
                         cudaFuncAttributeMaxDynamicSharedMemorySize, GEMM_SMEM);
    cudaFuncSetAttribute((const void*)attn_mma_kernel,
                         cudaFuncAttributeMaxDynamicSharedMemorySize, ATTN_SMEM);

    dim3 tb(32, 8), tg(32, 32, 4);
    transpose4_kernel<<<tg, tb>>>(Wk, Wq, Wv, Wp, pWt);

    dim3 gg(DIM / 128, RTOT / 128);   // (8, 32)
    // projections: tf32-round outputs (consumed by attention MMAs)
    gemm_mma_kernel<true><<<gg, 256, GEMM_SMEM>>>(kv, Wtk, bk, pK);
    gemm_mma_kernel<true><<<gg, 256, GEMM_SMEM>>>(q,  Wtq, bq, pQ);
    gemm_mma_kernel<true><<<gg, 256, GEMM_SMEM>>>(kv, Wtv, bv, pV);

    dim3 ga(SEQ / 64, NHEAD, 2);      // (32, 16, 2)
    attn_mma_kernel<<<ga, 256, ATTN_SMEM>>>(pQ, pK, pV, pY);

    // final projection: full fp32 output
    gemm_mma_kernel<false><<<gg, 256, GEMM_SMEM>>>(pY, Wtp, bp, out);
}

// round 6
// speedup vs baseline: 3.3268x; 1.1181x over previous
#include <cuda_runtime.h>
#include <cstdint>

// Problem constants: B=2, M=N=2048, C=D=1024, H=16, hd=64
#define RTOT 4096
#define DIM  1024
#define NHEAD 16
#define HD   64
#define SEQ  2048

// Scratch (device globals; no allocation allowed)
__device__ float g_K[2*2048*1024];
__device__ float g_Q[2*2048*1024];
__device__ float g_V[2*2048*1024];
__device__ float g_Y[2*2048*1024];
__device__ float g_Wt[4][1024*1024];   // transposed+tf32-rounded weights [Dout][Cin]

// ---------------------------------------------------------------------------
// helpers
// ---------------------------------------------------------------------------
__device__ __forceinline__ float tf32r(float x) {
    uint32_t y;
    asm("cvt.rna.tf32.f32 %0, %1;" : "=r"(y) : "f"(x));
    return __uint_as_float(y);
}
__device__ __forceinline__ uint32_t fu(float x) { return __float_as_uint(x); }
__device__ __forceinline__ uint32_t cvta_s(const void* p) {
    return (uint32_t)__cvta_generic_to_shared(p);
}

#define CP16(dst, src) \
    asm volatile("cp.async.cg.shared.global [%0], [%1], 16;" :: "r"(dst), "l"(src))
#define CPCOMMIT() asm volatile("cp.async.commit_group;")
#define CPWAIT(n)  asm volatile("cp.async.wait_group %0;" :: "n"(n))

#define LDSM4(r0, r1, r2, r3, addr) \
    asm volatile("ldmatrix.sync.aligned.m8n8.x4.shared.b16 {%0,%1,%2,%3}, [%4];" \
        : "=r"(r0), "=r"(r1), "=r"(r2), "=r"(r3) : "r"(addr))

#define CVTT(r) asm volatile("cvt.rna.tf32.f32 %0, %0;" : "+r"(r))

// m16n8k8 tf32 mma: D = A(16x8 row) * B(8x8 col) + D
__device__ __forceinline__ void mma8(float* c, const uint32_t* a, const uint32_t* b) {
    asm volatile(
        "mma.sync.aligned.m16n8k8.row.col.f32.tf32.tf32.f32 "
        "{%0,%1,%2,%3}, {%4,%5,%6,%7}, {%8,%9}, {%0,%1,%2,%3};"
        : "+f"(c[0]), "+f"(c[1]), "+f"(c[2]), "+f"(c[3])
        : "r"(a[0]), "r"(a[1]), "r"(a[2]), "r"(a[3]), "r"(b[0]), "r"(b[1]));
}

// ---------------------------------------------------------------------------
// Fused weight transpose + tf32 rounding: Wt[z][n][k] = tf32(W_z[k][n]).
// grid (32, 32, 4), block (32, 8)
// ---------------------------------------------------------------------------
__global__ void transpose4_kernel(const float* __restrict__ W0,
                                  const float* __restrict__ W1,
                                  const float* __restrict__ W2,
                                  const float* __restrict__ W3,
                                  float* __restrict__ WtAll)
{
    __shared__ float tile[32][33];
    const float* W = (blockIdx.z == 0) ? W0 : (blockIdx.z == 1) ? W1 :
                     (blockIdx.z == 2) ? W2 : W3;
    float* Wt = WtAll + (size_t)blockIdx.z * 1024 * 1024;
    int x = blockIdx.x * 32 + threadIdx.x;
    int y = blockIdx.y * 32 + threadIdx.y;
#pragma unroll
    for (int j = 0; j < 32; j += 8)
        tile[threadIdx.y + j][threadIdx.x] = W[(size_t)(y + j) * 1024 + x];
    __syncthreads();
    x = blockIdx.y * 32 + threadIdx.x;
    y = blockIdx.x * 32 + threadIdx.y;
#pragma unroll
    for (int j = 0; j < 32; j += 8)
        Wt[(size_t)(y + j) * 1024 + x] = tf32r(tile[threadIdx.x][threadIdx.y + j]);
}

// ---------------------------------------------------------------------------
// tf32 mma.sync GEMM body: Y[4096,1024] = X @ Wt^T + bias.  Wt is [Dout][Cin].
// 128x128 CTA tile, BK=32, 8 warps (4M x 2N), warp tile 32x64.
// RA: round A fragments (X not tf32-pre-rounded). RO: round outputs.
// ---------------------------------------------------------------------------
#define GSM_BUF 4608            // 128 * 36 floats
template<bool RA, bool RO>
__device__ __forceinline__
void gemm_body(const float* __restrict__ X, const float* __restrict__ Wt,
               const float* __restrict__ bias, float* __restrict__ Y,
               float* sm)
{
    float* As = sm;                 // 2 * 4608
    float* Bs = sm + 2 * GSM_BUF;   // 2 * 4608
    const uint32_t sA = cvta_s(As), sB = cvta_s(Bs);

    const int t  = threadIdx.x;
    const int w  = t >> 5, l = t & 31;
    const int wm = w & 3, wn = w >> 2;
    const int row0 = blockIdx.y * 128;
    const int col0 = blockIdx.x * 128;

    const int lrow = l & 15;
    const int lcA  = (l >> 4) * 4;
    const int lrB  = (l & 7) + (l >> 4) * 8;
    const int lcB  = ((l >> 3) & 1) * 4;

    float c[2][8][4];
#pragma unroll
    for (int i = 0; i < 2; i++)
#pragma unroll
        for (int j = 0; j < 8; j++)
#pragma unroll
            for (int r = 0; r < 4; r++) c[i][j][r] = 0.f;

    auto issue = [&](int s) {
        const int k0 = s * 32;
        const uint32_t dA = sA + (uint32_t)((s & 1) * GSM_BUF * 4);
        const uint32_t dB = sB + (uint32_t)((s & 1) * GSM_BUF * 4);
#pragma unroll
        for (int i = 0; i < 4; i++) {
            int f = t + i * 256;            // 0..1023
            int r = f >> 3, k4 = (f & 7) * 4;
            CP16(dA + (uint32_t)((r * 36 + k4) * 4),
                 X + (size_t)(row0 + r) * DIM + k0 + k4);
            CP16(dB + (uint32_t)((r * 36 + k4) * 4),
                 Wt + (size_t)(col0 + r) * DIM + k0 + k4);
        }
        CPCOMMIT();
    };

    issue(0);
    for (int s = 0; s < 32; s++) {
        if (s < 31) { issue(s + 1); CPWAIT(1); }
        else        { CPWAIT(0); }
        __syncthreads();

        const uint32_t bA = sA + (uint32_t)((s & 1) * GSM_BUF * 4);
        const uint32_t bB = sB + (uint32_t)((s & 1) * GSM_BUF * 4);
        const uint32_t a0a = bA + (uint32_t)(((wm * 32 + lrow) * 36 + lcA) * 4);
        const uint32_t b0a = bB + (uint32_t)(((wn * 64 + lrB) * 36 + lcB) * 4);

#pragma unroll
        for (int kk = 0; kk < 4; kk++) {
            uint32_t af[2][4], bf[8][2];
#pragma unroll
            for (int i = 0; i < 2; i++) {
                LDSM4(af[i][0], af[i][1], af[i][2], af[i][3],
                      a0a + (uint32_t)(i * 16 * 36 * 4 + kk * 32));
                if (RA) {
                    CVTT(af[i][0]); CVTT(af[i][1]); CVTT(af[i][2]); CVTT(af[i][3]);
                }
            }
#pragma unroll
            for (int jp = 0; jp < 4; jp++) {
                uint32_t q0, q1, q2, q3;
                LDSM4(q0, q1, q2, q3,
                      b0a + (uint32_t)(jp * 16 * 36 * 4 + kk * 32));
                bf[2*jp][0] = q0; bf[2*jp][1] = q1;
                bf[2*jp+1][0] = q2; bf[2*jp+1][1] = q3;
            }
#pragma unroll
            for (int i = 0; i < 2; i++)
#pragma unroll
                for (int j = 0; j < 8; j++)
                    mma8(c[i][j], af[i], bf[j]);
        }
        __syncthreads();
    }

    const int lg = l >> 2, lt = l & 3;
#pragma unroll
    for (int i = 0; i < 2; i++) {
        int r0 = row0 + wm * 32 + i * 16 + lg;
#pragma unroll
        for (int j = 0; j < 8; j++) {
            int cc = col0 + wn * 64 + j * 8 + 2 * lt;
            float2 bb = *(const float2*)(bias + cc);
            float2 o0 = { c[i][j][0] + bb.x, c[i][j][1] + bb.y };
            float2 o1 = { c[i][j][2] + bb.x, c[i][j][3] + bb.y };
            if (RO) {
                o0.x = tf32r(o0.x); o0.y = tf32r(o0.y);
                o1.x = tf32r(o1.x); o1.y = tf32r(o1.y);
            }
            *(float2*)(Y + (size_t)r0 * DIM + cc)       = o0;
            *(float2*)(Y + (size_t)(r0 + 8) * DIM + cc) = o1;
        }
    }
}

// Fused K/Q/V projection: grid.z selects which GEMM.
__global__ __launch_bounds__(256)
void gemm3_kernel(const float* __restrict__ kv, const float* __restrict__ q,
                  const float* __restrict__ WtAll,
                  const float* __restrict__ bk, const float* __restrict__ bq,
                  const float* __restrict__ bv,
                  float* __restrict__ K, float* __restrict__ Q,
                  float* __restrict__ V)
{
    extern __shared__ float sm[];
    const int z = blockIdx.z;
    const float* X    = (z == 1) ? q : kv;
    const float* Wt   = WtAll + (size_t)z * 1024 * 1024;
    const float* bias = (z == 0) ? bk : (z == 1) ? bq : bv;
    float* Y          = (z == 0) ? K  : (z == 1) ? Q  : V;
    gemm_body<true, true>(X, Wt, bias, Y, sm);
}

// Final projection: Y (pre-rounded) @ Wp^T + bp -> out (full fp32)
__global__ __launch_bounds__(256)
void gemmP_kernel(const float* __restrict__ Yin, const float* __restrict__ Wtp,
                  const float* __restrict__ bp, float* __restrict__ out)
{
    extern __shared__ float sm[];
    gemm_body<false, false>(Yin, Wtp, bp, out, sm);
}

// ---------------------------------------------------------------------------
// Flash attention on tf32 mma.sync, BQ=128, BK=64.
// Grid (SEQ/128, H, B), 256 threads (8 warps: 4 wm x 2 wn).
// Warp: S tile 32q x 32k (2 m-subtiles), O tile 32q x 32dv.
// SMEM: Qs[128][68], Ks[64][68], Ps[128][68], Vs[64][72], m/l/corr[128].
// All inputs pre-rounded to tf32 by projection epilogues.
// ---------------------------------------------------------------------------
__global__ __launch_bounds__(256, 2)
void attn_mma_kernel(const float* __restrict__ Q, const float* __restrict__ K,
                     const float* __restrict__ V, float* __restrict__ Y)
{
    extern __shared__ float sm[];
    float* Qs   = sm;               // 128*68 = 8704
    float* Ks   = sm + 8704;        // 64*68  = 4352
    float* Ps   = sm + 13056;       // 128*68 = 8704
    float* Vs   = sm + 21760;       // 64*72  = 4608
    float* mrow = sm + 26368;       // 128
    float* lsum = sm + 26496;       // 128
    float* corr = sm + 26624;       // 128   (total 26752 floats)
    const uint32_t sQ = cvta_s(Qs), sK = cvta_s(Ks), sP = cvta_s(Ps),
                   sV = cvta_s(Vs);

    const int t  = threadIdx.x;
    const int w  = t >> 5, l = t & 31;
    const int wm = w & 3, wn = w >> 2;
    const int lg = l >> 2, lt = l & 3;
    const int lrow = l & 15;
    const int lcA  = (l >> 4) * 4;
    const int lrB  = (l & 7) + (l >> 4) * 8;
    const int lcB  = ((l >> 3) & 1) * 4;
    const int n0 = blockIdx.x * 128;
    const size_t base = (size_t)blockIdx.z * SEQ * DIM + (size_t)blockIdx.y * HD;
    const float scale = 0.125f;

    // Q tile (128 x 64) via cp.async
#pragma unroll
    for (int it = 0; it < 8; it++) {
        int f = t + it * 256;           // 0..2047
        int r = f >> 4, c4 = (f & 15) * 4;
        CP16(sQ + (uint32_t)((r * 68 + c4) * 4),
             Q + base + (size_t)(n0 + r) * DIM + c4);
    }
    CPCOMMIT();
    if (t < 128) { mrow[t] = -1e30f; lsum[t] = 0.f; }

    float o[2][4][4];
#pragma unroll
    for (int i = 0; i < 2; i++)
#pragma unroll
        for (int j = 0; j < 4; j++)
#pragma unroll
            for (int r = 0; r < 4; r++) o[i][j][r] = 0.f;

    for (int kt = 0; kt < SEQ / 64; kt++) {
        __syncthreads();   // prev-iter reads of Ks/Vs/Ps done
        // load K and V tiles (64 x 64 each)
#pragma unroll
        for (int it = 0; it < 4; it++) {
            int f = t + it * 256;
            int r = f >> 4, c4 = (f & 15) * 4;
            size_t gi = base + (size_t)(kt * 64 + r) * DIM + c4;
            CP16(sK + (uint32_t)((r * 68 + c4) * 4), K + gi);
            CP16(sV + (uint32_t)((r * 72 + c4) * 4), V + gi);
        }
        CPCOMMIT(); CPWAIT(0);
        __syncthreads();

        // S = Q K^T : warp computes 32(q) x 32(k)
        float s4[2][4][4];
#pragma unroll
        for (int i = 0; i < 2; i++)
#pragma unroll
            for (int j = 0; j < 4; j++)
#pragma unroll
                for (int r = 0; r < 4; r++) s4[i][j][r] = 0.f;

        const uint32_t kb = sK + (uint32_t)(((wn * 32 + lrB) * 68 + lcB) * 4);
#pragma unroll
        for (int kk = 0; kk < 8; kk++) {
            uint32_t af[2][4];
#pragma unroll
            for (int i = 0; i < 2; i++) {
                const uint32_t qb = sQ +
                    (uint32_t)(((wm * 32 + i * 16 + lrow) * 68 + lcA) * 4);
                LDSM4(af[i][0], af[i][1], af[i][2], af[i][3],
                      qb + (uint32_t)(kk * 32));
            }
#pragma unroll
            for (int jp = 0; jp < 2; jp++) {
                uint32_t q0, q1, q2, q3;
                LDSM4(q0, q1, q2, q3,
                      kb + (uint32_t)(jp * 16 * 68 * 4 + kk * 32));
                uint32_t bf0[2] = { q0, q1 }, bf1[2] = { q2, q3 };
#pragma unroll
                for (int i = 0; i < 2; i++) {
                    mma8(s4[i][2*jp],   af[i], bf0);
                    mma8(s4[i][2*jp+1], af[i], bf1);
                }
            }
        }

        // store S fragments into Ps (as [q][k_local])
#pragma unroll
        for (int i = 0; i < 2; i++) {
            int rr = wm * 32 + i * 16 + lg;
#pragma unroll
            for (int j = 0; j < 4; j++) {
                int cc = wn * 32 + j * 8 + 2 * lt;
                *(float2*)(Ps + rr * 68 + cc) =
                    make_float2(s4[i][j][0], s4[i][j][1]);
                *(float2*)(Ps + (rr + 8) * 68 + cc) =
                    make_float2(s4[i][j][2], s4[i][j][3]);
            }
        }
        __syncthreads();

        // softmax: 2 lanes per q-row, 32 cols each
        {
            int row = t >> 1, sub = t & 1;
            float* rp = Ps + row * 68 + sub * 32;
            float4 v[8];
#pragma unroll
            for (int x = 0; x < 8; x++) v[x] = *(float4*)(rp + x * 4);
            float vmax = -1e30f;
#pragma unroll
            for (int x = 0; x < 8; x++)
                vmax = fmaxf(vmax, fmaxf(fmaxf(v[x].x, v[x].y),
                                         fmaxf(v[x].z, v[x].w)));
            vmax = fmaxf(vmax, __shfl_xor_sync(0xffffffffu, vmax, 1));
            float mprev = mrow[row];
            float newm  = fmaxf(mprev, vmax * scale);
            float cv    = __expf(mprev - newm);
            float ps = 0.f;
#pragma unroll
            for (int x = 0; x < 8; x++) {
                float4 e;
                e.x = __expf(fmaf(v[x].x, scale, -newm));
                e.y = __expf(fmaf(v[x].y, scale, -newm));
                e.z = __expf(fmaf(v[x].z, scale, -newm));
                e.w = __expf(fmaf(v[x].w, scale, -newm));
                ps += (e.x + e.y) + (e.z + e.w);
                e.x = tf32r(e.x); e.y = tf32r(e.y);
                e.z = tf32r(e.z); e.w = tf32r(e.w);
                *(float4*)(rp + x * 4) = e;
            }
            ps += __shfl_xor_sync(0xffffffffu, ps, 1);
            if (sub == 0) {
                mrow[row] = newm;
                lsum[row] = lsum[row] * cv + ps;
                corr[row] = cv;
            }
        }
        __syncthreads();

        // rescale O, then O += P V
#pragma unroll
        for (int i = 0; i < 2; i++) {
            float c0 = corr[wm * 32 + i * 16 + lg];
            float c1 = corr[wm * 32 + i * 16 + 8 + lg];
#pragma unroll
            for (int j = 0; j < 4; j++) {
                o[i][j][0] *= c0; o[i][j][1] *= c0;
                o[i][j][2] *= c1; o[i][j][3] *= c1;
            }
        }
#pragma unroll
        for (int kk = 0; kk < 8; kk++) {
            uint32_t af[2][4];
#pragma unroll
            for (int i = 0; i < 2; i++) {
                const uint32_t pb = sP +
                    (uint32_t)(((wm * 32 + i * 16 + lrow) * 68 + lcA) * 4);
                LDSM4(af[i][0], af[i][1], af[i][2], af[i][3],
                      pb + (uint32_t)(kk * 32));
            }
#pragma unroll
            for (int j = 0; j < 4; j++) {
                const float* bp = Vs + (kk * 8 + lt) * 72 + wn * 32 + j * 8 + lg;
                uint32_t bf[2] = { fu(bp[0]), fu(bp[4 * 72]) };
#pragma unroll
                for (int i = 0; i < 2; i++)
                    mma8(o[i][j], af[i], bf);
            }
        }
    }

    // final: divide by lsum, tf32-round (consumed by final GEMM), write out
#pragma unroll
    for (int i = 0; i < 2; i++) {
        float i0 = 1.0f / lsum[wm * 32 + i * 16 + lg];
        float i1 = 1.0f / lsum[wm * 32 + i * 16 + 8 + lg];
        int r0 = n0 + wm * 32 + i * 16 + lg;
#pragma unroll
        for (int j = 0; j < 4; j++) {
            int cc = wn * 32 + j * 8 + 2 * lt;
            *(float2*)(Y + base + (size_t)r0 * DIM + cc) =
                make_float2(tf32r(o[i][j][0] * i0), tf32r(o[i][j][1] * i0));
            *(float2*)(Y + base + (size_t)(r0 + 8) * DIM + cc) =
                make_float2(tf32r(o[i][j][2] * i1), tf32r(o[i][j][3] * i1));
        }
    }
}

// ---------------------------------------------------------------------------
// Inputs: kv, q, Wk, bk, Wq, bq, Wv, bv, Wp, bp
// ---------------------------------------------------------------------------
extern "C" void kernel_launch(void* const* d_in, const int* in_sizes, int n_in,
                              void* d_out, int out_size)
{
    const float* kv = (const float*)d_in[0];
    const float* q  = (const float*)d_in[1];
    const float* Wk = (const float*)d_in[2];
    const float* bk = (const float*)d_in[3];
    const float* Wq = (const float*)d_in[4];
    const float* bq = (const float*)d_in[5];
    const float* Wv = (const float*)d_in[6];
    const float* bv = (const float*)d_in[7];
    const float* Wp = (const float*)d_in[8];
    const float* bp = (const float*)d_in[9];
    float* out = (float*)d_out;

    float *pK, *pQ, *pV, *pY, *pWt;
    cudaGetSymbolAddress((void**)&pK, g_K);
    cudaGetSymbolAddress((void**)&pQ, g_Q);
    cudaGetSymbolAddress((void**)&pV, g_V);
    cudaGetSymbolAddress((void**)&pY, g_Y);
    cudaGetSymbolAddress((void**)&pWt, g_Wt);
    float* Wtp = pWt + 3 * 1024 * 1024;

    const int GEMM_SMEM = 4 * GSM_BUF * 4;   // 73728 B
    const int ATTN_SMEM = 26752 * 4;         // 107008 B
    cudaFuncSetAttribute((const void*)gemm3_kernel,
                         cudaFuncAttributeMaxDynamicSharedMemorySize, GEMM_SMEM);
    cudaFuncSetAttribute((const void*)gemmP_kernel,
                         cudaFuncAttributeMaxDynamicSharedMemorySize, GEMM_SMEM);
    cudaFuncSetAttribute((const void*)attn_mma_kernel,
                         cudaFuncAttributeMaxDynamicSharedMemorySize, ATTN_SMEM);

    dim3 tb(32, 8), tg(32, 32, 4);
    transpose4_kernel<<<tg, tb>>>(Wk, Wq, Wv, Wp, pWt);

    dim3 g3(DIM / 128, RTOT / 128, 3);   // (8, 32, 3) = 768 CTAs
    gemm3_kernel<<<g3, 256, GEMM_SMEM>>>(kv, q, pWt, bk, bq, bv, pK, pQ, pV);

    dim3 ga(SEQ / 128, NHEAD, 2);        // (16, 16, 2) = 512 CTAs
    attn_mma_kernel<<<ga, 256, ATTN_SMEM>>>(pQ, pK, pV, pY);

    dim3 gg(DIM / 128, RTOT / 128);      // (8, 32)
    gemmP_kernel<<<gg, 256, GEMM_SMEM>>>(pY, Wtp, bp, out);
}

// round 7
// speedup vs baseline: 3.3849x; 1.0175x over previous
#include <cuda_runtime.h>
#include <cstdint>

// Problem constants: B=2, M=N=2048, C=D=1024, H=16, hd=64
#define RTOT 4096
#define DIM  1024
#define NHEAD 16
#define HD   64
#define SEQ  2048

// Scratch (device globals; no allocation allowed)
__device__ float g_K[2*2048*1024];
__device__ float g_Q[2*2048*1024];
__device__ float g_V[2*2048*1024];
__device__ float g_Y[2*2048*1024];
__device__ float g_Wt[4][1024*1024];   // transposed+tf32-rounded weights [Dout][Cin]

// ---------------------------------------------------------------------------
// helpers
// ---------------------------------------------------------------------------
__device__ __forceinline__ float tf32r(float x) {
    uint32_t y;
    asm("cvt.rna.tf32.f32 %0, %1;" : "=r"(y) : "f"(x));
    return __uint_as_float(y);
}
__device__ __forceinline__ uint32_t fu(float x) { return __float_as_uint(x); }
__device__ __forceinline__ uint32_t cvta_s(const void* p) {
    return (uint32_t)__cvta_generic_to_shared(p);
}

#define CP16(dst, src) \
    asm volatile("cp.async.cg.shared.global [%0], [%1], 16;" :: "r"(dst), "l"(src))
#define CPCOMMIT() asm volatile("cp.async.commit_group;")
#define CPWAIT(n)  asm volatile("cp.async.wait_group %0;" :: "n"(n))

#define LDSM4(r0, r1, r2, r3, addr) \
    asm volatile("ldmatrix.sync.aligned.m8n8.x4.shared.b16 {%0,%1,%2,%3}, [%4];" \
        : "=r"(r0), "=r"(r1), "=r"(r2), "=r"(r3) : "r"(addr))

#define CVTT(r) asm volatile("cvt.rna.tf32.f32 %0, %0;" : "+r"(r))

// m16n8k8 tf32 mma: D = A(16x8 row) * B(8x8 col) + D
__device__ __forceinline__ void mma8(float* c, const uint32_t* a, const uint32_t* b) {
    asm volatile(
        "mma.sync.aligned.m16n8k8.row.col.f32.tf32.tf32.f32 "
        "{%0,%1,%2,%3}, {%4,%5,%6,%7}, {%8,%9}, {%0,%1,%2,%3};"
        : "+f"(c[0]), "+f"(c[1]), "+f"(c[2]), "+f"(c[3])
        : "r"(a[0]), "r"(a[1]), "r"(a[2]), "r"(a[3]), "r"(b[0]), "r"(b[1]));
}

// ---------------------------------------------------------------------------
// Fused weight transpose + tf32 rounding: Wt[z][n][k] = tf32(W_z[k][n]).
// grid (32, 32, 4), block (32, 8)
// ---------------------------------------------------------------------------
__global__ void transpose4_kernel(const float* __restrict__ W0,
                                  const float* __restrict__ W1,
                                  const float* __restrict__ W2,
                                  const float* __restrict__ W3,
                                  float* __restrict__ WtAll)
{
    __shared__ float tile[32][33];
    const float* W = (blockIdx.z == 0) ? W0 : (blockIdx.z == 1) ? W1 :
                     (blockIdx.z == 2) ? W2 : W3;
    float* Wt = WtAll + (size_t)blockIdx.z * 1024 * 1024;
    int x = blockIdx.x * 32 + threadIdx.x;
    int y = blockIdx.y * 32 + threadIdx.y;
#pragma unroll
    for (int j = 0; j < 32; j += 8)
        tile[threadIdx.y + j][threadIdx.x] = W[(size_t)(y + j) * 1024 + x];
    __syncthreads();
    x = blockIdx.y * 32 + threadIdx.x;
    y = blockIdx.x * 32 + threadIdx.y;
#pragma unroll
    for (int j = 0; j < 32; j += 8)
        Wt[(size_t)(y + j) * 1024 + x] = tf32r(tile[threadIdx.x][threadIdx.y + j]);
}

// ---------------------------------------------------------------------------
// tf32 mma.sync GEMM body: Y[4096,1024] = X @ Wt^T + bias.  Wt is [Dout][Cin].
// 128x128 CTA tile, BK=32, 4 warps (2M x 2N), warp tile 64x64.
// 3-stage cp.async ring, ONE barrier per stage.
// RA: round A fragments. RO: round outputs.
// ---------------------------------------------------------------------------
#define GSM_BUF 4608            // 128 * 36 floats
template<bool RA, bool RO>
__device__ __forceinline__
void gemm_body(const float* __restrict__ X, const float* __restrict__ Wt,
               const float* __restrict__ bias, float* __restrict__ Y,
               float* sm)
{
    float* As = sm;                 // 3 * 4608
    float* Bs = sm + 3 * GSM_BUF;   // 3 * 4608
    const uint32_t sA = cvta_s(As), sB = cvta_s(Bs);

    const int t  = threadIdx.x;     // 128 threads, 4 warps
    const int w  = t >> 5, l = t & 31;
    const int wm = w & 1, wn = w >> 1;
    const int row0 = blockIdx.y * 128;
    const int col0 = blockIdx.x * 128;

    const int lrow = l & 15;
    const int lcA  = (l >> 4) * 4;
    const int lrB  = (l & 7) + (l >> 4) * 8;
    const int lcB  = ((l >> 3) & 1) * 4;

    float c[4][8][4];
#pragma unroll
    for (int i = 0; i < 4; i++)
#pragma unroll
        for (int j = 0; j < 8; j++)
#pragma unroll
            for (int r = 0; r < 4; r++) c[i][j][r] = 0.f;

    auto issue = [&](int s) {
        const int k0 = s * 32;
        const uint32_t dA = sA + (uint32_t)((s % 3) * GSM_BUF * 4);
        const uint32_t dB = sB + (uint32_t)((s % 3) * GSM_BUF * 4);
#pragma unroll
        for (int i = 0; i < 8; i++) {
            int f = t + i * 128;            // 0..1023
            int r = f >> 3, k4 = (f & 7) * 4;
            CP16(dA + (uint32_t)((r * 36 + k4) * 4),
                 X + (size_t)(row0 + r) * DIM + k0 + k4);
            CP16(dB + (uint32_t)((r * 36 + k4) * 4),
                 Wt + (size_t)(col0 + r) * DIM + k0 + k4);
        }
        CPCOMMIT();
    };

    issue(0); issue(1);
    for (int s = 0; s < 32; s++) {
        if (s == 31) { CPWAIT(0); } else { CPWAIT(1); }
        __syncthreads();                 // buf s visible; all done with buf (s+2)%3
        if (s + 2 < 32) issue(s + 2);

        const uint32_t bA = sA + (uint32_t)((s % 3) * GSM_BUF * 4);
        const uint32_t bB = sB + (uint32_t)((s % 3) * GSM_BUF * 4);
        const uint32_t a0a = bA + (uint32_t)(((wm * 64 + lrow) * 36 + lcA) * 4);
        const uint32_t b0a = bB + (uint32_t)(((wn * 64 + lrB) * 36 + lcB) * 4);

#pragma unroll
        for (int kk = 0; kk < 4; kk++) {
            uint32_t af[4][4], bf[8][2];
#pragma unroll
            for (int i = 0; i < 4; i++) {
                LDSM4(af[i][0], af[i][1], af[i][2], af[i][3],
                      a0a + (uint32_t)(i * 16 * 36 * 4 + kk * 32));
                if (RA) {
                    CVTT(af[i][0]); CVTT(af[i][1]); CVTT(af[i][2]); CVTT(af[i][3]);
                }
            }
#pragma unroll
            for (int jp = 0; jp < 4; jp++) {
                uint32_t q0, q1, q2, q3;
                LDSM4(q0, q1, q2, q3,
                      b0a + (uint32_t)(jp * 16 * 36 * 4 + kk * 32));
                bf[2*jp][0] = q0; bf[2*jp][1] = q1;
                bf[2*jp+1][0] = q2; bf[2*jp+1][1] = q3;
            }
#pragma unroll
            for (int i = 0; i < 4; i++)
#pragma unroll
                for (int j = 0; j < 8; j++)
                    mma8(c[i][j], af[i], bf[j]);
        }
    }

    const int lg = l >> 2, lt = l & 3;
#pragma unroll
    for (int i = 0; i < 4; i++) {
        int r0 = row0 + wm * 64 + i * 16 + lg;
#pragma unroll
        for (int j = 0; j < 8; j++) {
            int cc = col0 + wn * 64 + j * 8 + 2 * lt;
            float2 bb = *(const float2*)(bias + cc);
            float2 o0 = { c[i][j][0] + bb.x, c[i][j][1] + bb.y };
            float2 o1 = { c[i][j][2] + bb.x, c[i][j][3] + bb.y };
            if (RO) {
                o0.x = tf32r(o0.x); o0.y = tf32r(o0.y);
                o1.x = tf32r(o1.x); o1.y = tf32r(o1.y);
            }
            *(float2*)(Y + (size_t)r0 * DIM + cc)       = o0;
            *(float2*)(Y + (size_t)(r0 + 8) * DIM + cc) = o1;
        }
    }
}

// Fused K/Q/V projection: grid.z selects which GEMM.
__global__ __launch_bounds__(128)
void gemm3_kernel(const float* __restrict__ kv, const float* __restrict__ q,
                  const float* __restrict__ WtAll,
                  const float* __restrict__ bk, const float* __restrict__ bq,
                  const float* __restrict__ bv,
                  float* __restrict__ K, float* __restrict__ Q,
                  float* __restrict__ V)
{
    extern __shared__ float sm[];
    const int z = blockIdx.z;
    const float* X    = (z == 1) ? q : kv;
    const float* Wt   = WtAll + (size_t)z * 1024 * 1024;
    const float* bias = (z == 0) ? bk : (z == 1) ? bq : bv;
    float* Y          = (z == 0) ? K  : (z == 1) ? Q  : V;
    gemm_body<true, true>(X, Wt, bias, Y, sm);
}

// Final projection: Y (pre-rounded) @ Wp^T + bp -> out (full fp32)
__global__ __launch_bounds__(128)
void gemmP_kernel(const float* __restrict__ Yin, const float* __restrict__ Wtp,
                  const float* __restrict__ bp, float* __restrict__ out)
{
    extern __shared__ float sm[];
    gemm_body<false, false>(Yin, Wtp, bp, out, sm);
}

// ---------------------------------------------------------------------------
// Flash attention on tf32 mma.sync, BQ=128, BK=64.
// Grid (SEQ/128, H, B), 256 threads (8 warps: 4 wm x 2 wn).
// K[kt+1] prefetched during softmax+PV of kt; V[kt+1] during S of kt+1.
// All loads hidden; 4 barriers/kt. Scale folded into S-store.
// ---------------------------------------------------------------------------
__global__ __launch_bounds__(256, 2)
void attn_mma_kernel(const float* __restrict__ Q, const float* __restrict__ K,
                     const float* __restrict__ V, float* __restrict__ Y)
{
    extern __shared__ float sm[];
    float* Qs   = sm;               // 128*68 = 8704
    float* Ks   = sm + 8704;        // 64*68  = 4352
    float* Ps   = sm + 13056;       // 128*68 = 8704
    float* Vs   = sm + 21760;       // 64*72  = 4608
    float* mrow = sm + 26368;       // 128
    float* lsum = sm + 26496;       // 128
    float* corr = sm + 26624;       // 128   (total 26752 floats)
    const uint32_t sQ = cvta_s(Qs), sK = cvta_s(Ks), sP = cvta_s(Ps),
                   sV = cvta_s(Vs);

    const int t  = threadIdx.x;
    const int w  = t >> 5, l = t & 31;
    const int wm = w & 3, wn = w >> 2;
    const int lg = l >> 2, lt = l & 3;
    const int lrow = l & 15;
    const int lcA  = (l >> 4) * 4;
    const int lrB  = (l & 7) + (l >> 4) * 8;
    const int lcB  = ((l >> 3) & 1) * 4;
    const int n0 = blockIdx.x * 128;
    const size_t base = (size_t)blockIdx.z * SEQ * DIM + (size_t)blockIdx.y * HD;
    const float scale = 0.125f;
    const int NT = SEQ / 64;

    auto issueK = [&](int kt) {
#pragma unroll
        for (int it = 0; it < 4; it++) {
            int f = t + it * 256;
            int r = f >> 4, c4 = (f & 15) * 4;
            CP16(sK + (uint32_t)((r * 68 + c4) * 4),
                 K + base + (size_t)(kt * 64 + r) * DIM + c4);
        }
        CPCOMMIT();
    };
    auto issueV = [&](int kt) {
#pragma unroll
        for (int it = 0; it < 4; it++) {
            int f = t + it * 256;
            int r = f >> 4, c4 = (f & 15) * 4;
            CP16(sV + (uint32_t)((r * 72 + c4) * 4),
                 V + base + (size_t)(kt * 64 + r) * DIM + c4);
        }
        CPCOMMIT();
    };

    // prologue: Q tile, then K0, then V0 (three groups, oldest first)
#pragma unroll
    for (int it = 0; it < 8; it++) {
        int f = t + it * 256;           // 0..2047
        int r = f >> 4, c4 = (f & 15) * 4;
        CP16(sQ + (uint32_t)((r * 68 + c4) * 4),
             Q + base + (size_t)(n0 + r) * DIM + c4);
    }
    CPCOMMIT();
    issueK(0);
    issueV(0);
    if (t < 128) { mrow[t] = -1e30f; lsum[t] = 0.f; }

    float o[2][4][4];
#pragma unroll
    for (int i = 0; i < 2; i++)
#pragma unroll
        for (int j = 0; j < 4; j++)
#pragma unroll
            for (int r = 0; r < 4; r++) o[i][j][r] = 0.f;

    for (int kt = 0; kt < NT; kt++) {
        CPWAIT(1);          // Q+K[kt] complete (V[kt] may still be in flight)
        __syncthreads();    // K visible block-wide; all warps past prev PV

        // S = Q K^T : warp computes 32(q) x 32(k)
        float s4[2][4][4];
#pragma unroll
        for (int i = 0; i < 2; i++)
#pragma unroll
            for (int j = 0; j < 4; j++)
#pragma unroll
                for (int r = 0; r < 4; r++) s4[i][j][r] = 0.f;

        const uint32_t kb = sK + (uint32_t)(((wn * 32 + lrB) * 68 + lcB) * 4);
#pragma unroll
        for (int kk = 0; kk < 8; kk++) {
            uint32_t af[2][4];
#pragma unroll
            for (int i = 0; i < 2; i++) {
                const uint32_t qb = sQ +
                    (uint32_t)(((wm * 32 + i * 16 + lrow) * 68 + lcA) * 4);
                LDSM4(af[i][0], af[i][1], af[i][2], af[i][3],
                      qb + (uint32_t)(kk * 32));
            }
#pragma unroll
            for (int jp = 0; jp < 2; jp++) {
                uint32_t q0, q1, q2, q3;
                LDSM4(q0, q1, q2, q3,
                      kb + (uint32_t)(jp * 16 * 68 * 4 + kk * 32));
                uint32_t bf0[2] = { q0, q1 }, bf1[2] = { q2, q3 };
#pragma unroll
                for (int i = 0; i < 2; i++) {
                    mma8(s4[i][2*jp],   af[i], bf0);
                    mma8(s4[i][2*jp+1], af[i], bf1);
                }
            }
        }

        // store scale*S into Ps
#pragma unroll
        for (int i = 0; i < 2; i++) {
            int rr = wm * 32 + i * 16 + lg;
#pragma unroll
            for (int j = 0; j < 4; j++) {
                int cc = wn * 32 + j * 8 + 2 * lt;
                *(float2*)(Ps + rr * 68 + cc) =
                    make_float2(s4[i][j][0] * scale, s4[i][j][1] * scale);
                *(float2*)(Ps + (rr + 8) * 68 + cc) =
                    make_float2(s4[i][j][2] * scale, s4[i][j][3] * scale);
            }
        }
        __syncthreads();            // S complete; K buffer free
        if (kt + 1 < NT) issueK(kt + 1);   // overlaps softmax + PV

        // softmax: 2 lanes per q-row, 32 cols each (logits pre-scaled)
        {
            int row = t >> 1, sub = t & 1;
            float* rp = Ps + row * 68 + sub * 32;
            float4 v[8];
#pragma unroll
            for (int x = 0; x < 8; x++) v[x] = *(float4*)(rp + x * 4);
            float vmax = -1e30f;
#pragma unroll
            for (int x = 0; x < 8; x++)
                vmax = fmaxf(vmax, fmaxf(fmaxf(v[x].x, v[x].y),
                                         fmaxf(v[x].z, v[x].w)));
            vmax = fmaxf(vmax, __shfl_xor_sync(0xffffffffu, vmax, 1));
            float mprev = mrow[row];
            float newm  = fmaxf(mprev, vmax);
            float cv    = __expf(mprev - newm);
            float ps = 0.f;
#pragma unroll
            for (int x = 0; x < 8; x++) {
                float4 e;
                e.x = __expf(v[x].x - newm);
                e.y = __expf(v[x].y - newm);
                e.z = __expf(v[x].z - newm);
                e.w = __expf(v[x].w - newm);
                ps += (e.x + e.y) + (e.z + e.w);
                e.x = tf32r(e.x); e.y = tf32r(e.y);
                e.z = tf32r(e.z); e.w = tf32r(e.w);
                *(float4*)(rp + x * 4) = e;
            }
            ps += __shfl_xor_sync(0xffffffffu, ps, 1);
            if (sub == 0) {
                mrow[row] = newm;
                lsum[row] = lsum[row] * cv + ps;
                corr[row] = cv;
            }
        }
        if (kt + 1 < NT) { CPWAIT(1); } else { CPWAIT(0); }   // V[kt] done
        __syncthreads();            // Ps + V visible block-wide

        // rescale O, then O += P V
#pragma unroll
        for (int i = 0; i < 2; i++) {
            float c0 = corr[wm * 32 + i * 16 + lg];
            float c1 = corr[wm * 32 + i * 16 + 8 + lg];
#pragma unroll
            for (int j = 0; j < 4; j++) {
                o[i][j][0] *= c0; o[i][j][1] *= c0;
                o[i][j][2] *= c1; o[i][j][3] *= c1;
            }
        }
#pragma unroll
        for (int kk = 0; kk < 8; kk++) {
            uint32_t af[2][4];
#pragma unroll
            for (int i = 0; i < 2; i++) {
                const uint32_t pb = sP +
                    (uint32_t)(((wm * 32 + i * 16 + lrow) * 68 + lcA) * 4);
                LDSM4(af[i][0], af[i][1], af[i][2], af[i][3],
                      pb + (uint32_t)(kk * 32));
            }
#pragma unroll
            for (int j = 0; j < 4; j++) {
                const float* bp = Vs + (kk * 8 + lt) * 72 + wn * 32 + j * 8 + lg;
                uint32_t bf[2] = { fu(bp[0]), fu(bp[4 * 72]) };
#pragma unroll
                for (int i = 0; i < 2; i++)
                    mma8(o[i][j], af[i], bf);
            }
        }
        __syncthreads();            // PV done; V buffer free
        if (kt + 1 < NT) issueV(kt + 1);   // overlaps next S + softmax
    }

    // final: divide by lsum, tf32-round (consumed by final GEMM), write out
#pragma unroll
    for (int i = 0; i < 2; i++) {
        float i0 = 1.0f / lsum[wm * 32 + i * 16 + lg];
        float i1 = 1.0f / lsum[wm * 32 + i * 16 + 8 + lg];
        int r0 = n0 + wm * 32 + i * 16 + lg;
#pragma unroll
        for (int j = 0; j < 4; j++) {
            int cc = wn * 32 + j * 8 + 2 * lt;
            *(float2*)(Y + base + (size_t)r0 * DIM + cc) =
                make_float2(tf32r(o[i][j][0] * i0), tf32r(o[i][j][1] * i0));
            *(float2*)(Y + base + (size_t)(r0 + 8) * DIM + cc) =
                make_float2(tf32r(o[i][j][2] * i1), tf32r(o[i][j][3] * i1));
        }
    }
}

// ---------------------------------------------------------------------------
// Inputs: kv, q, Wk, bk, Wq, bq, Wv, bv, Wp, bp
// ---------------------------------------------------------------------------
extern "C" void kernel_launch(void* const* d_in, const int* in_sizes, int n_in,
                              void* d_out, int out_size)
{
    const float* kv = (const float*)d_in[0];
    const float* q  = (const float*)d_in[1];
    const float* Wk = (const float*)d_in[2];
    const float* bk = (const float*)d_in[3];
    const float* Wq = (const float*)d_in[4];
    const float* bq = (const float*)d_in[5];
    const float* Wv = (const float*)d_in[6];
    const float* bv = (const float*)d_in[7];
    const float* Wp = (const float*)d_in[8];
    const float* bp = (const float*)d_in[9];
    float* out = (float*)d_out;

    float *pK, *pQ, *pV, *pY, *pWt;
    cudaGetSymbolAddress((void**)&pK, g_K);
    cudaGetSymbolAddress((void**)&pQ, g_Q);
    cudaGetSymbolAddress((void**)&pV, g_V);
    cudaGetSymbolAddress((void**)&pY, g_Y);
    cudaGetSymbolAddress((void**)&pWt, g_Wt);
    float* Wtp = pWt + 3 * 1024 * 1024;

    const int GEMM_SMEM = 6 * GSM_BUF * 4;   // 110592 B (3-stage ring)
    const int ATTN_SMEM = 26752 * 4;         // 107008 B
    cudaFuncSetAttribute((const void*)gemm3_kernel,
                         cudaFuncAttributeMaxDynamicSharedMemorySize, GEMM_SMEM);
    cudaFuncSetAttribute((const void*)gemmP_kernel,
                         cudaFuncAttributeMaxDynamicSharedMemorySize, GEMM_SMEM);
    cudaFuncSetAttribute((const void*)attn_mma_kernel,
                         cudaFuncAttributeMaxDynamicSharedMemorySize, ATTN_SMEM);

    dim3 tb(32, 8), tg(32, 32, 4);
    transpose4_kernel<<<tg, tb>>>(Wk, Wq, Wv, Wp, pWt);

    dim3 g3(DIM / 128, RTOT / 128, 3);   // (8, 32, 3) = 768 CTAs
    gemm3_kernel<<<g3, 128, GEMM_SMEM>>>(kv, q, pWt, bk, bq, bv, pK, pQ, pV);

    dim3 ga(SEQ / 128, NHEAD, 2);        // (16, 16, 2) = 512 CTAs
    attn_mma_kernel<<<ga, 256, ATTN_SMEM>>>(pQ, pK, pV, pY);

    dim3 gg(DIM / 128, RTOT / 128);      // (8, 32)
    gemmP_kernel<<<gg, 128, GEMM_SMEM>>>(pY, Wtp, bp, out);
}

// round 8
// speedup vs baseline: 3.9705x; 1.1730x over previous
#include <cuda_runtime.h>
#include <cstdint>

// Problem constants: B=2, M=N=2048, C=D=1024, H=16, hd=64
#define RTOT 4096
#define DIM  1024
#define NHEAD 16
#define HD   64
#define SEQ  2048

// Scratch (device globals; no allocation allowed)
__device__ float g_K[2*2048*1024];
__device__ float g_Q[2*2048*1024];
__device__ float g_V[2*2048*1024];
__device__ float g_Y[2*2048*1024];
__device__ float g_Wt[4][1024*1024];   // transposed+tf32-rounded weights [Dout][Cin]

// ---------------------------------------------------------------------------
// helpers
// ---------------------------------------------------------------------------
__device__ __forceinline__ float tf32r(float x) {
    uint32_t y;
    asm("cvt.rna.tf32.f32 %0, %1;" : "=r"(y) : "f"(x));
    return __uint_as_float(y);
}
__device__ __forceinline__ uint32_t fu(float x) { return __float_as_uint(x); }
__device__ __forceinline__ uint32_t cvta_s(const void* p) {
    return (uint32_t)__cvta_generic_to_shared(p);
}

#define CP16(dst, src) \
    asm volatile("cp.async.cg.shared.global [%0], [%1], 16;" :: "r"(dst), "l"(src))
#define CPCOMMIT() asm volatile("cp.async.commit_group;")
#define CPWAIT(n)  asm volatile("cp.async.wait_group %0;" :: "n"(n))

#define LDSM4(r0, r1, r2, r3, addr) \
    asm volatile("ldmatrix.sync.aligned.m8n8.x4.shared.b16 {%0,%1,%2,%3}, [%4];" \
        : "=r"(r0), "=r"(r1), "=r"(r2), "=r"(r3) : "r"(addr))

#define CVTT(r) asm volatile("cvt.rna.tf32.f32 %0, %0;" : "+r"(r))

// m16n8k8 tf32 mma: D = A(16x8 row) * B(8x8 col) + D
__device__ __forceinline__ void mma8(float* c, const uint32_t* a, const uint32_t* b) {
    asm volatile(
        "mma.sync.aligned.m16n8k8.row.col.f32.tf32.tf32.f32 "
        "{%0,%1,%2,%3}, {%4,%5,%6,%7}, {%8,%9}, {%0,%1,%2,%3};"
        : "+f"(c[0]), "+f"(c[1]), "+f"(c[2]), "+f"(c[3])
        : "r"(a[0]), "r"(a[1]), "r"(a[2]), "r"(a[3]), "r"(b[0]), "r"(b[1]));
}

// ---------------------------------------------------------------------------
// Fused weight transpose + tf32 rounding: Wt[z][n][k] = tf32(W_z[k][n]).
// grid (32, 32, 4), block (32, 8)
// ---------------------------------------------------------------------------
__global__ void transpose4_kernel(const float* __restrict__ W0,
                                  const float* __restrict__ W1,
                                  const float* __restrict__ W2,
                                  const float* __restrict__ W3,
                                  float* __restrict__ WtAll)
{
    __shared__ float tile[32][33];
    const float* W = (blockIdx.z == 0) ? W0 : (blockIdx.z == 1) ? W1 :
                     (blockIdx.z == 2) ? W2 : W3;
    float* Wt = WtAll + (size_t)blockIdx.z * 1024 * 1024;
    int x = blockIdx.x * 32 + threadIdx.x;
    int y = blockIdx.y * 32 + threadIdx.y;
#pragma unroll
    for (int j = 0; j < 32; j += 8)
        tile[threadIdx.y + j][threadIdx.x] = W[(size_t)(y + j) * 1024 + x];
    __syncthreads();
    x = blockIdx.y * 32 + threadIdx.x;
    y = blockIdx.x * 32 + threadIdx.y;
#pragma unroll
    for (int j = 0; j < 32; j += 8)
        Wt[(size_t)(y + j) * 1024 + x] = tf32r(tile[threadIdx.x][threadIdx.y + j]);
}

// ---------------------------------------------------------------------------
// tf32 mma.sync GEMM body: Y[4096,1024] = X @ Wt^T + bias.  Wt is [Dout][Cin].
// 128x128 CTA tile, BK=32, 4 warps (2M x 2N), warp tile 64x64.
// 2-stage cp.async ring, ONE barrier per stage, 73.7KB smem -> 2 CTA/SM.
// ---------------------------------------------------------------------------
#define GSM_BUF 4608            // 128 * 36 floats
template<bool RA, bool RO>
__device__ __forceinline__
void gemm_body(const float* __restrict__ X, const float* __restrict__ Wt,
               const float* __restrict__ bias, float* __restrict__ Y,
               float* sm)
{
    float* As = sm;                 // 2 * 4608
    float* Bs = sm + 2 * GSM_BUF;   // 2 * 4608
    const uint32_t sA = cvta_s(As), sB = cvta_s(Bs);

    const int t  = threadIdx.x;     // 128 threads, 4 warps
    const int w  = t >> 5, l = t & 31;
    const int wm = w & 1, wn = w >> 1;
    const int row0 = blockIdx.y * 128;
    const int col0 = blockIdx.x * 128;

    const int lrow = l & 15;
    const int lcA  = (l >> 4) * 4;
    const int lrB  = (l & 7) + (l >> 4) * 8;
    const int lcB  = ((l >> 3) & 1) * 4;

    float c[4][8][4];
#pragma unroll
    for (int i = 0; i < 4; i++)
#pragma unroll
        for (int j = 0; j < 8; j++)
#pragma unroll
            for (int r = 0; r < 4; r++) c[i][j][r] = 0.f;

    auto issue = [&](int s) {
        const int k0 = s * 32;
        const uint32_t dA = sA + (uint32_t)((s & 1) * GSM_BUF * 4);
        const uint32_t dB = sB + (uint32_t)((s & 1) * GSM_BUF * 4);
#pragma unroll
        for (int i = 0; i < 8; i++) {
            int f = t + i * 128;            // 0..1023
            int r = f >> 3, k4 = (f & 7) * 4;
            CP16(dA + (uint32_t)((r * 36 + k4) * 4),
                 X + (size_t)(row0 + r) * DIM + k0 + k4);
            CP16(dB + (uint32_t)((r * 36 + k4) * 4),
                 Wt + (size_t)(col0 + r) * DIM + k0 + k4);
        }
        CPCOMMIT();
    };

    issue(0);
    for (int s = 0; s < 32; s++) {
        CPWAIT(0);
        __syncthreads();            // buf s ready; buf s^1 fully consumed
        if (s + 1 < 32) issue(s + 1);

        const uint32_t bA = sA + (uint32_t)((s & 1) * GSM_BUF * 4);
        const uint32_t bB = sB + (uint32_t)((s & 1) * GSM_BUF * 4);
        const uint32_t a0a = bA + (uint32_t)(((wm * 64 + lrow) * 36 + lcA) * 4);
        const uint32_t b0a = bB + (uint32_t)(((wn * 64 + lrB) * 36 + lcB) * 4);

#pragma unroll
        for (int kk = 0; kk < 4; kk++) {
            uint32_t af[4][4], bf[8][2];
#pragma unroll
            for (int i = 0; i < 4; i++) {
                LDSM4(af[i][0], af[i][1], af[i][2], af[i][3],
                      a0a + (uint32_t)(i * 16 * 36 * 4 + kk * 32));
                if (RA) {
                    CVTT(af[i][0]); CVTT(af[i][1]); CVTT(af[i][2]); CVTT(af[i][3]);
                }
            }
#pragma unroll
            for (int jp = 0; jp < 4; jp++) {
                uint32_t q0, q1, q2, q3;
                LDSM4(q0, q1, q2, q3,
                      b0a + (uint32_t)(jp * 16 * 36 * 4 + kk * 32));
                bf[2*jp][0] = q0; bf[2*jp][1] = q1;
                bf[2*jp+1][0] = q2; bf[2*jp+1][1] = q3;
            }
#pragma unroll
            for (int i = 0; i < 4; i++)
#pragma unroll
                for (int j = 0; j < 8; j++)
                    mma8(c[i][j], af[i], bf[j]);
        }
        __syncthreads();            // all warps done with buf s before refill
    }

    const int lg = l >> 2, lt = l & 3;
#pragma unroll
    for (int i = 0; i < 4; i++) {
        int r0 = row0 + wm * 64 + i * 16 + lg;
#pragma unroll
        for (int j = 0; j < 8; j++) {
            int cc = col0 + wn * 64 + j * 8 + 2 * lt;
            float2 bb = *(const float2*)(bias + cc);
            float2 o0 = { c[i][j][0] + bb.x, c[i][j][1] + bb.y };
            float2 o1 = { c[i][j][2] + bb.x, c[i][j][3] + bb.y };
            if (RO) {
                o0.x = tf32r(o0.x); o0.y = tf32r(o0.y);
                o1.x = tf32r(o1.x); o1.y = tf32r(o1.y);
            }
            *(float2*)(Y + (size_t)r0 * DIM + cc)       = o0;
            *(float2*)(Y + (size_t)(r0 + 8) * DIM + cc) = o1;
        }
    }
}

// Fused K/Q/V projection: grid.z selects which GEMM.
__global__ __launch_bounds__(128)
void gemm3_kernel(const float* __restrict__ kv, const float* __restrict__ q,
                  const float* __restrict__ WtAll,
                  const float* __restrict__ bk, const float* __restrict__ bq,
                  const float* __restrict__ bv,
                  float* __restrict__ K, float* __restrict__ Q,
                  float* __restrict__ V)
{
    extern __shared__ float sm[];
    const int z = blockIdx.z;
    const float* X    = (z == 1) ? q : kv;
    const float* Wt   = WtAll + (size_t)z * 1024 * 1024;
    const float* bias = (z == 0) ? bk : (z == 1) ? bq : bv;
    float* Y          = (z == 0) ? K  : (z == 1) ? Q  : V;
    gemm_body<true, true>(X, Wt, bias, Y, sm);
}

// Final projection: Y (pre-rounded) @ Wp^T + bp -> out (full fp32)
__global__ __launch_bounds__(128)
void gemmP_kernel(const float* __restrict__ Yin, const float* __restrict__ Wtp,
                  const float* __restrict__ bp, float* __restrict__ out)
{
    extern __shared__ float sm[];
    gemm_body<false, false>(Yin, Wtp, bp, out, sm);
}

// ---------------------------------------------------------------------------
// Flash attention, FA2-style: 4 warps, each owns 32 q-rows x full 64 k-cols.
// Softmax state (m, l, corr) entirely in registers (quad shfl reductions).
// BQ=128, BK=64. Grid (SEQ/128, H, B), 128 threads.
// SMEM: Qs[128][68], Ks[64][68], Ps[128][68], Vs[64][72] = 105.5KB, 2 CTA/SM.
// K[kt+1] prefetched during softmax/PV; V[kt+1] during next S.
// ---------------------------------------------------------------------------
__global__ __launch_bounds__(128, 2)
void attn_mma_kernel(const float* __restrict__ Q, const float* __restrict__ K,
                     const float* __restrict__ V, float* __restrict__ Y)
{
    extern __shared__ float sm[];
    float* Qs = sm;               // 128*68 = 8704
    float* Ks = sm + 8704;        // 64*68  = 4352
    float* Ps = sm + 13056;       // 128*68 = 8704
    float* Vs = sm + 21760;       // 64*72  = 4608   (total 26368 floats)
    const uint32_t sQ = cvta_s(Qs), sK = cvta_s(Ks), sP = cvta_s(Ps),
                   sV = cvta_s(Vs);

    const int t  = threadIdx.x;   // 128 threads, 4 warps
    const int w  = t >> 5, l = t & 31;
    const int lg = l >> 2, lt = l & 3;
    const int lrow = l & 15;
    const int lcA  = (l >> 4) * 4;
    const int lrB  = (l & 7) + (l >> 4) * 8;
    const int lcB  = ((l >> 3) & 1) * 4;
    const int n0 = blockIdx.x * 128;
    const size_t base = (size_t)blockIdx.z * SEQ * DIM + (size_t)blockIdx.y * HD;
    const float scale = 0.125f;
    const int NT = SEQ / 64;

    auto issueK = [&](int kt) {
#pragma unroll
        for (int it = 0; it < 8; it++) {
            int f = t + it * 128;
            int r = f >> 4, c4 = (f & 15) * 4;
            CP16(sK + (uint32_t)((r * 68 + c4) * 4),
                 K + base + (size_t)(kt * 64 + r) * DIM + c4);
        }
        CPCOMMIT();
    };
    auto issueV = [&](int kt) {
#pragma unroll
        for (int it = 0; it < 8; it++) {
            int f = t + it * 128;
            int r = f >> 4, c4 = (f & 15) * 4;
            CP16(sV + (uint32_t)((r * 72 + c4) * 4),
                 V + base + (size_t)(kt * 64 + r) * DIM + c4);
        }
        CPCOMMIT();
    };

    // prologue: Q tile, then K0, then V0 (groups oldest-first)
#pragma unroll
    for (int it = 0; it < 16; it++) {
        int f = t + it * 128;           // 0..2047
        int r = f >> 4, c4 = (f & 15) * 4;
        CP16(sQ + (uint32_t)((r * 68 + c4) * 4),
             Q + base + (size_t)(n0 + r) * DIM + c4);
    }
    CPCOMMIT();
    issueK(0);
    issueV(0);

    // register softmax state: [i][h]  (i = 16-row subtile, h = lg / lg+8)
    float m_[2][2] = {{-1e30f, -1e30f}, {-1e30f, -1e30f}};
    float l_[2][2] = {{0.f, 0.f}, {0.f, 0.f}};

    float o[2][8][4];
#pragma unroll
    for (int i = 0; i < 2; i++)
#pragma unroll
        for (int j = 0; j < 8; j++)
#pragma unroll
            for (int r = 0; r < 4; r++) o[i][j][r] = 0.f;

    for (int kt = 0; kt < NT; kt++) {
        CPWAIT(1);          // K[kt] complete (V[kt] may be in flight)
        __syncthreads();    // K visible block-wide; all warps past prev PV

        // S = Q K^T : warp computes 32(q) x 64(k)
        float s4[2][8][4];
#pragma unroll
        for (int i = 0; i < 2; i++)
#pragma unroll
            for (int j = 0; j < 8; j++)
#pragma unroll
                for (int r = 0; r < 4; r++) s4[i][j][r] = 0.f;

#pragma unroll
        for (int kk = 0; kk < 8; kk++) {
            uint32_t af[2][4];
#pragma unroll
            for (int i = 0; i < 2; i++) {
                const uint32_t qb = sQ +
                    (uint32_t)(((w * 32 + i * 16 + lrow) * 68 + lcA) * 4);
                LDSM4(af[i][0], af[i][1], af[i][2], af[i][3],
                      qb + (uint32_t)(kk * 32));
            }
#pragma unroll
            for (int jp = 0; jp < 4; jp++) {
                uint32_t q0, q1, q2, q3;
                const uint32_t kb = sK +
                    (uint32_t)(((jp * 16 + lrB) * 68 + lcB) * 4);
                LDSM4(q0, q1, q2, q3, kb + (uint32_t)(kk * 32));
                uint32_t bf0[2] = { q0, q1 }, bf1[2] = { q2, q3 };
#pragma unroll
                for (int i = 0; i < 2; i++) {
                    mma8(s4[i][2*jp],   af[i], bf0);
                    mma8(s4[i][2*jp+1], af[i], bf1);
                }
            }
        }
        __syncthreads();            // all warps done reading Ks
        if (kt + 1 < NT) issueK(kt + 1);   // overlaps softmax + PV

        // register online softmax (rows fully warp-local; quad reduction)
#pragma unroll
        for (int i = 0; i < 2; i++) {
#pragma unroll
            for (int h = 0; h < 2; h++) {
                float vmax = -1e30f;
#pragma unroll
                for (int j = 0; j < 8; j++)
                    vmax = fmaxf(vmax, fmaxf(s4[i][j][2*h], s4[i][j][2*h+1]));
                vmax = fmaxf(vmax, __shfl_xor_sync(0xffffffffu, vmax, 1));
                vmax = fmaxf(vmax, __shfl_xor_sync(0xffffffffu, vmax, 2));
                float newm = fmaxf(m_[i][h], vmax * scale);
                float cv   = __expf(m_[i][h] - newm);
                m_[i][h] = newm;
                float ps = 0.f;
#pragma unroll
                for (int j = 0; j < 8; j++) {
                    float e0 = __expf(fmaf(s4[i][j][2*h],   scale, -newm));
                    float e1 = __expf(fmaf(s4[i][j][2*h+1], scale, -newm));
                    ps += e0 + e1;
                    s4[i][j][2*h]   = tf32r(e0);
                    s4[i][j][2*h+1] = tf32r(e1);
                }
                ps += __shfl_xor_sync(0xffffffffu, ps, 1);
                ps += __shfl_xor_sync(0xffffffffu, ps, 2);
                l_[i][h] = l_[i][h] * cv + ps;
                // rescale O for this row group
#pragma unroll
                for (int j = 0; j < 8; j++) {
                    o[i][j][2*h]   *= cv;
                    o[i][j][2*h+1] *= cv;
                }
            }
            // store exp'd P to warp-private Ps rows
            int rr = w * 32 + i * 16 + lg;
#pragma unroll
            for (int j = 0; j < 8; j++) {
                *(float2*)(Ps + rr * 68 + j * 8 + 2 * lt) =
                    make_float2(s4[i][j][0], s4[i][j][1]);
                *(float2*)(Ps + (rr + 8) * 68 + j * 8 + 2 * lt) =
                    make_float2(s4[i][j][2], s4[i][j][3]);
            }
        }

        if (kt + 1 < NT) { CPWAIT(1); } else { CPWAIT(0); }   // V[kt] done
        __syncthreads();            // V + Ps visible block-wide

        // O += P V
#pragma unroll
        for (int kk = 0; kk < 8; kk++) {
            uint32_t af[2][4];
#pragma unroll
            for (int i = 0; i < 2; i++) {
                const uint32_t pb = sP +
                    (uint32_t)(((w * 32 + i * 16 + lrow) * 68 + lcA) * 4);
                LDSM4(af[i][0], af[i][1], af[i][2], af[i][3],
                      pb + (uint32_t)(kk * 32));
            }
#pragma unroll
            for (int j = 0; j < 8; j++) {
                const float* bp = Vs + (kk * 8 + lt) * 72 + j * 8 + lg;
                uint32_t bf[2] = { fu(bp[0]), fu(bp[4 * 72]) };
#pragma unroll
                for (int i = 0; i < 2; i++)
                    mma8(o[i][j], af[i], bf);
            }
        }
        __syncthreads();            // PV done; V buffer free
        if (kt + 1 < NT) issueV(kt + 1);   // overlaps next S
    }

    // final: divide by lsum, tf32-round (consumed by final GEMM), write out
#pragma unroll
    for (int i = 0; i < 2; i++) {
        float i0 = 1.0f / l_[i][0];
        float i1 = 1.0f / l_[i][1];
        int r0 = n0 + w * 32 + i * 16 + lg;
#pragma unroll
        for (int j = 0; j < 8; j++) {
            int cc = j * 8 + 2 * lt;
            *(float2*)(Y + base + (size_t)r0 * DIM + cc) =
                make_float2(tf32r(o[i][j][0] * i0), tf32r(o[i][j][1] * i0));
            *(float2*)(Y + base + (size_t)(r0 + 8) * DIM + cc) =
                make_float2(tf32r(o[i][j][2] * i1), tf32r(o[i][j][3] * i1));
        }
    }
}

// ---------------------------------------------------------------------------
// Inputs: kv, q, Wk, bk, Wq, bq, Wv, bv, Wp, bp
// ---------------------------------------------------------------------------
extern "C" void kernel_launch(void* const* d_in, const int* in_sizes, int n_in,
                              void* d_out, int out_size)
{
    const float* kv = (const float*)d_in[0];
    const float* q  = (const float*)d_in[1];
    const float* Wk = (const float*)d_in[2];
    const float* bk = (const float*)d_in[3];
    const float* Wq = (const float*)d_in[4];
    const float* bq = (const float*)d_in[5];
    const float* Wv = (const float*)d_in[6];
    const float* bv = (const float*)d_in[7];
    const float* Wp = (const float*)d_in[8];
    const float* bp = (const float*)d_in[9];
    float* out = (float*)d_out;

    float *pK, *pQ, *pV, *pY, *pWt;
    cudaGetSymbolAddress((void**)&pK, g_K);
    cudaGetSymbolAddress((void**)&pQ, g_Q);
    cudaGetSymbolAddress((void**)&pV, g_V);
    cudaGetSymbolAddress((void**)&pY, g_Y);
    cudaGetSymbolAddress((void**)&pWt, g_Wt);
    float* Wtp = pWt + 3 * 1024 * 1024;

    const int GEMM_SMEM = 4 * GSM_BUF * 4;   // 73728 B (2-stage ring)
    const int ATTN_SMEM = 26368 * 4;         // 105472 B
    cudaFuncSetAttribute((const void*)gemm3_kernel,
                         cudaFuncAttributeMaxDynamicSharedMemorySize, GEMM_SMEM);
    cudaFuncSetAttribute((const void*)gemmP_kernel,
                         cudaFuncAttributeMaxDynamicSharedMemorySize, GEMM_SMEM);
    cudaFuncSetAttribute((const void*)attn_mma_kernel,
                         cudaFuncAttributeMaxDynamicSharedMemorySize, ATTN_SMEM);

    dim3 tb(32, 8), tg(32, 32, 4);
    transpose4_kernel<<<tg, tb>>>(Wk, Wq, Wv, Wp, pWt);

    dim3 g3(DIM / 128, RTOT / 128, 3);   // (8, 32, 3) = 768 CTAs
    gemm3_kernel<<<g3, 128, GEMM_SMEM>>>(kv, q, pWt, bk, bq, bv, pK, pQ, pV);

    dim3 ga(SEQ / 128, NHEAD, 2);        // (16, 16, 2) = 512 CTAs
    attn_mma_kernel<<<ga, 128, ATTN_SMEM>>>(pQ, pK, pV, pY);

    dim3 gg(DIM / 128, RTOT / 128);      // (8, 32)
    gemmP_kernel<<<gg, 128, GEMM_SMEM>>>(pY, Wtp, bp, out);
}

// round 10
// speedup vs baseline: 6.4121x; 1.6150x over previous
#include <cuda_runtime.h>
#include <cuda_fp16.h>
#include <cstdint>

// Problem constants: B=2, M=N=2048, C=D=1024, H=16, hd=64
#define RTOT 4096
#define DIM  1024
#define NHEAD 16
#define HD   64
#define SEQ  2048

// Scratch (device globals; no allocation allowed)
__device__ __half g_Kh[2*2048*1024];
__device__ __half g_Qh[2*2048*1024];
__device__ __half g_Vh[2*2048*1024];
__device__ __half g_Yh[2*2048*1024];
__device__ __half g_kvh[2*2048*1024];
__device__ __half g_qh[2*2048*1024];
__device__ __half g_Wth[4][1024*1024];   // transposed fp16 weights [Dout][Cin]

// ---------------------------------------------------------------------------
// helpers
// ---------------------------------------------------------------------------
__device__ __forceinline__ uint32_t cvta_s(const void* p) {
    return (uint32_t)__cvta_generic_to_shared(p);
}
__device__ __forceinline__ uint32_t h2u(__half2 h) {
    return *(uint32_t*)&h;
}

#define CP16(dst, src) \
    asm volatile("cp.async.cg.shared.global [%0], [%1], 16;" :: "r"(dst), "l"(src))
#define CPCOMMIT() asm volatile("cp.async.commit_group;")
#define CPWAIT(n)  asm volatile("cp.async.wait_group %0;" :: "n"(n))

#define LDSM4(r0, r1, r2, r3, addr) \
    asm volatile("ldmatrix.sync.aligned.m8n8.x4.shared.b16 {%0,%1,%2,%3}, [%4];" \
        : "=r"(r0), "=r"(r1), "=r"(r2), "=r"(r3) : "r"(addr))
#define LDSM4T(r0, r1, r2, r3, addr) \
    asm volatile("ldmatrix.sync.aligned.m8n8.x4.trans.shared.b16 {%0,%1,%2,%3}, [%4];" \
        : "=r"(r0), "=r"(r1), "=r"(r2), "=r"(r3) : "r"(addr))

// m16n8k16 fp16 mma, fp32 accumulate
__device__ __forceinline__ void mma16(float* c, const uint32_t* a, const uint32_t* b) {
    asm volatile(
        "mma.sync.aligned.m16n8k16.row.col.f32.f16.f16.f32 "
        "{%0,%1,%2,%3}, {%4,%5,%6,%7}, {%8,%9}, {%0,%1,%2,%3};"
        : "+f"(c[0]), "+f"(c[1]), "+f"(c[2]), "+f"(c[3])
        : "r"(a[0]), "r"(a[1]), "r"(a[2]), "r"(a[3]), "r"(b[0]), "r"(b[1]));
}

// ---------------------------------------------------------------------------
// Weight transpose + fp16: Wt[z][n][k] = fp16(W_z[k][n]). grid(32,32,4)
// ---------------------------------------------------------------------------
__global__ void transpose4_kernel(const float* __restrict__ W0,
                                  const float* __restrict__ W1,
                                  const float* __restrict__ W2,
                                  const float* __restrict__ W3,
                                  __half* __restrict__ WtAll)
{
    __shared__ float tile[32][33];
    const float* W = (blockIdx.z == 0) ? W0 : (blockIdx.z == 1) ? W1 :
                     (blockIdx.z == 2) ? W2 : W3;
    __half* Wt = WtAll + (size_t)blockIdx.z * 1024 * 1024;
    int x = blockIdx.x * 32 + threadIdx.x;
    int y = blockIdx.y * 32 + threadIdx.y;
#pragma unroll
    for (int j = 0; j < 32; j += 8)
        tile[threadIdx.y + j][threadIdx.x] = W[(size_t)(y + j) * 1024 + x];
    __syncthreads();
    x = blockIdx.y * 32 + threadIdx.x;
    y = blockIdx.x * 32 + threadIdx.y;
#pragma unroll
    for (int j = 0; j < 32; j += 8)
        Wt[(size_t)(y + j) * 1024 + x] = __float2half_rn(tile[threadIdx.x][threadIdx.y + j]);
}

// fp32 -> fp16 convert for kv and q. grid (2048, 1, 2), block 256.
__global__ void cvt_fp16_kernel(const float* __restrict__ a, const float* __restrict__ b,
                                __half* __restrict__ da, __half* __restrict__ db)
{
    const float* src = blockIdx.z ? b : a;
    __half* dst = blockIdx.z ? db : da;
    size_t i = ((size_t)blockIdx.x * 256 + threadIdx.x) * 8;
    float4 v0 = *(const float4*)(src + i);
    float4 v1 = *(const float4*)(src + i + 4);
    uint4 u;
    u.x = h2u(__floats2half2_rn(v0.x, v0.y));
    u.y = h2u(__floats2half2_rn(v0.z, v0.w));
    u.z = h2u(__floats2half2_rn(v1.x, v1.y));
    u.w = h2u(__floats2half2_rn(v1.z, v1.w));
    *(uint4*)(dst + i) = u;
}

// ---------------------------------------------------------------------------
// fp16 mma GEMM: Y[4096,1024] = X @ Wt^T + bias (fp32 accum).
// 128x128 CTA tile, BK=32, 4 warps (2M x 2N), warp tile 64x64.
// 2-stage cp.async ring; smem 40KB; 3 CTA/SM.
// SMEM rows stride 40 halves (80B) -> conflict-free ldmatrix.
// ---------------------------------------------------------------------------
#define GSMH 5120               // 128 * 40 halves per buffer
template<bool OUT_HALF>
__device__ __forceinline__
void gemm_body(const __half* __restrict__ X, const __half* __restrict__ Wt,
               const float* __restrict__ bias, void* __restrict__ Yout,
               __half* smh)
{
    const uint32_t sA = cvta_s(smh);
    const uint32_t sB = sA + 2 * GSMH * 2;

    const int t  = threadIdx.x;     // 128 threads, 4 warps
    const int w  = t >> 5, l = t & 31;
    const int wm = w & 1, wn = w >> 1;
    const int row0 = blockIdx.y * 128;
    const int col0 = blockIdx.x * 128;

    const int lr = l & 15;          // ldmatrix row within 16-row tile
    const int lc = (l >> 4) * 8;    // ldmatrix col half-select (halves)

    float c[4][8][4];
#pragma unroll
    for (int i = 0; i < 4; i++)
#pragma unroll
        for (int j = 0; j < 8; j++)
#pragma unroll
            for (int r = 0; r < 4; r++) c[i][j][r] = 0.f;

    auto issue = [&](int s) {
        const int k0 = s * 32;      // halves
        const uint32_t dA = sA + (uint32_t)((s & 1) * GSMH * 2);
        const uint32_t dB = sB + (uint32_t)((s & 1) * GSMH * 2);
#pragma unroll
        for (int i = 0; i < 4; i++) {
            int f = t + i * 128;            // 0..511
            int r = f >> 2, k8 = (f & 3) * 8;
            CP16(dA + (uint32_t)((r * 40 + k8) * 2),
                 X + (size_t)(row0 + r) * DIM + k0 + k8);
            CP16(dB + (uint32_t)((r * 40 + k8) * 2),
                 Wt + (size_t)(col0 + r) * DIM + k0 + k8);
        }
        CPCOMMIT();
    };

    issue(0);
    for (int s = 0; s < 32; s++) {
        CPWAIT(0);
        __syncthreads();
        if (s + 1 < 32) issue(s + 1);

        const uint32_t bA = sA + (uint32_t)((s & 1) * GSMH * 2);
        const uint32_t bB = sB + (uint32_t)((s & 1) * GSMH * 2);

#pragma unroll
        for (int ks = 0; ks < 2; ks++) {
            uint32_t af[4][4];
#pragma unroll
            for (int i = 0; i < 4; i++) {
                const uint32_t aa = bA +
                    (uint32_t)(((wm * 64 + i * 16 + lr) * 40 + ks * 16 + lc) * 2);
                LDSM4(af[i][0], af[i][1], af[i][2], af[i][3], aa);
            }
#pragma unroll
            for (int g = 0; g < 4; g++) {
                uint32_t q0, q1, q2, q3;
                const uint32_t ba = bB +
                    (uint32_t)(((wn * 64 + g * 16 + lr) * 40 + ks * 16 + lc) * 2);
                LDSM4(q0, q1, q2, q3, ba);
                uint32_t bf0[2] = { q0, q2 };   // n-group 2g
                uint32_t bf1[2] = { q1, q3 };   // n-group 2g+1
#pragma unroll
                for (int i = 0; i < 4; i++) {
                    mma16(c[i][2*g],   af[i], bf0);
                    mma16(c[i][2*g+1], af[i], bf1);
                }
            }
        }
        __syncthreads();
    }

    const int lg = l >> 2, lt = l & 3;
#pragma unroll
    for (int i = 0; i < 4; i++) {
        int r0 = row0 + wm * 64 + i * 16 + lg;
#pragma unroll
        for (int j = 0; j < 8; j++) {
            int cc = col0 + wn * 64 + j * 8 + 2 * lt;
            float2 bb = *(const float2*)(bias + cc);
            float o0x = c[i][j][0] + bb.x, o0y = c[i][j][1] + bb.y;
            float o1x = c[i][j][2] + bb.x, o1y = c[i][j][3] + bb.y;
            if (OUT_HALF) {
                __half* Y = (__half*)Yout;
                *(__half2*)(Y + (size_t)r0 * DIM + cc)       = __floats2half2_rn(o0x, o0y);
                *(__half2*)(Y + (size_t)(r0 + 8) * DIM + cc) = __floats2half2_rn(o1x, o1y);
            } else {
                float* Y = (float*)Yout;
                *(float2*)(Y + (size_t)r0 * DIM + cc)       = make_float2(o0x, o0y);
                *(float2*)(Y + (size_t)(r0 + 8) * DIM + cc) = make_float2(o1x, o1y);
            }
        }
    }
}

// Fused K/Q/V projection: grid.z selects which GEMM.
__global__ __launch_bounds__(128, 3)
void gemm3_kernel(const __half* __restrict__ kvh, const __half* __restrict__ qh,
                  const __half* __restrict__ WtAll,
                  const float* __restrict__ bk, const float* __restrict__ bq,
                  const float* __restrict__ bv,
                  __half* __restrict__ K, __half* __restrict__ Q,
                  __half* __restrict__ V)
{
    extern __shared__ __half smh[];
    const int z = blockIdx.z;
    const __half* X    = (z == 1) ? qh : kvh;
    const __half* Wt   = WtAll + (size_t)z * 1024 * 1024;
    const float* bias  = (z == 0) ? bk : (z == 1) ? bq : bv;
    __half* Y          = (z == 0) ? K  : (z == 1) ? Q  : V;
    gemm_body<true>(X, Wt, bias, Y, smh);
}

// Final projection: Yh fp16 @ Wp^T + bp -> out fp32
__global__ __launch_bounds__(128, 3)
void gemmP_kernel(const __half* __restrict__ Yin, const __half* __restrict__ Wtp,
                  const float* __restrict__ bp, float* __restrict__ out)
{
    extern __shared__ __half smh[];
    gemm_body<false>(Yin, Wtp, bp, out, smh);
}

// ---------------------------------------------------------------------------
// Flash attention, fp16 mma (fp32 accum/softmax). 4 warps, each 32q x 64k.
// BQ=128, BK=64. Grid (SEQ/128, H, B), 128 threads.
// SMEM halves (stride 72): Qs[128]=9216, Ks[64]=4608, Ps[128]=9216,
// Vs[64]=4608 -> offsets 0 / 9216 / 13824 / 23040, total 27648 h = 55296 B.
// K[kt+1] prefetched during softmax/PV; V[kt+1] during next S.
// ---------------------------------------------------------------------------
#define QS_OFF 0
#define KS_OFF 9216
#define PS_OFF 13824
#define VS_OFF 23040
__global__ __launch_bounds__(128, 2)
void attn_mma_kernel(const __half* __restrict__ Q, const __half* __restrict__ K,
                     const __half* __restrict__ V, __half* __restrict__ Y)
{
    extern __shared__ __half smh[];
    __half* Ps_h = smh + PS_OFF;
    const uint32_t sQ = cvta_s(smh);
    const uint32_t sK = sQ + KS_OFF * 2;
    const uint32_t sP = sQ + PS_OFF * 2;
    const uint32_t sV = sQ + VS_OFF * 2;

    const int t  = threadIdx.x;   // 128 threads, 4 warps
    const int w  = t >> 5, l = t & 31;
    const int lg = l >> 2, lt = l & 3;
    const int lr = l & 15;
    const int lc = (l >> 4) * 8;
    const int n0 = blockIdx.x * 128;
    const size_t base = (size_t)blockIdx.z * SEQ * DIM + (size_t)blockIdx.y * HD;
    const float scale = 0.125f;
    const int NT = SEQ / 64;

    auto issueK = [&](int kt) {
#pragma unroll
        for (int it = 0; it < 4; it++) {
            int f = t + it * 128;           // 0..511
            int r = f >> 3, c8 = (f & 7) * 8;
            CP16(sK + (uint32_t)((r * 72 + c8) * 2),
                 K + base + (size_t)(kt * 64 + r) * DIM + c8);
        }
        CPCOMMIT();
    };
    auto issueV = [&](int kt) {
#pragma unroll
        for (int it = 0; it < 4; it++) {
            int f = t + it * 128;
            int r = f >> 3, c8 = (f & 7) * 8;
            CP16(sV + (uint32_t)((r * 72 + c8) * 2),
                 V + base + (size_t)(kt * 64 + r) * DIM + c8);
        }
        CPCOMMIT();
    };

    // prologue: Q tile, K0, V0 (groups oldest-first)
#pragma unroll
    for (int it = 0; it < 8; it++) {
        int f = t + it * 128;               // 0..1023
        int r = f >> 3, c8 = (f & 7) * 8;
        CP16(sQ + (uint32_t)((r * 72 + c8) * 2),
             Q + base + (size_t)(n0 + r) * DIM + c8);
    }
    CPCOMMIT();
    issueK(0);
    issueV(0);

    float m_[2][2] = {{-1e30f, -1e30f}, {-1e30f, -1e30f}};
    float l_[2][2] = {{0.f, 0.f}, {0.f, 0.f}};

    float o[2][8][4];
#pragma unroll
    for (int i = 0; i < 2; i++)
#pragma unroll
        for (int j = 0; j < 8; j++)
#pragma unroll
            for (int r = 0; r < 4; r++) o[i][j][r] = 0.f;

    for (int kt = 0; kt < NT; kt++) {
        CPWAIT(1);          // K[kt] ready (V[kt] may be in flight)
        __syncthreads();

        // S = Q K^T : 32(q) x 64(k) per warp, 4 ksteps of 16
        float s4[2][8][4];
#pragma unroll
        for (int i = 0; i < 2; i++)
#pragma unroll
            for (int j = 0; j < 8; j++)
#pragma unroll
                for (int r = 0; r < 4; r++) s4[i][j][r] = 0.f;

#pragma unroll
        for (int ks = 0; ks < 4; ks++) {
            uint32_t af[2][4];
#pragma unroll
            for (int i = 0; i < 2; i++) {
                const uint32_t qa = sQ +
                    (uint32_t)(((w * 32 + i * 16 + lr) * 72 + ks * 16 + lc) * 2);
                LDSM4(af[i][0], af[i][1], af[i][2], af[i][3], qa);
            }
#pragma unroll
            for (int g = 0; g < 4; g++) {
                uint32_t q0, q1, q2, q3;
                const uint32_t ka = sK +
                    (uint32_t)(((g * 16 + lr) * 72 + ks * 16 + lc) * 2);
                LDSM4(q0, q1, q2, q3, ka);
                uint32_t bf0[2] = { q0, q2 };
                uint32_t bf1[2] = { q1, q3 };
#pragma unroll
                for (int i = 0; i < 2; i++) {
                    mma16(s4[i][2*g],   af[i], bf0);
                    mma16(s4[i][2*g+1], af[i], bf1);
                }
            }
        }
        __syncthreads();            // all warps done reading Ks
        if (kt + 1 < NT) issueK(kt + 1);

        // register online softmax + fp16 P store
#pragma unroll
        for (int i = 0; i < 2; i++) {
#pragma unroll
            for (int h = 0; h < 2; h++) {
                float vmax = -1e30f;
#pragma unroll
                for (int j = 0; j < 8; j++)
                    vmax = fmaxf(vmax, fmaxf(s4[i][j][2*h], s4[i][j][2*h+1]));
                vmax = fmaxf(vmax, __shfl_xor_sync(0xffffffffu, vmax, 1));
                vmax = fmaxf(vmax, __shfl_xor_sync(0xffffffffu, vmax, 2));
                float newm = fmaxf(m_[i][h], vmax * scale);
                float cv   = __expf(m_[i][h] - newm);
                m_[i][h] = newm;
                float ps = 0.f;
#pragma unroll
                for (int j = 0; j < 8; j++) {
                    float e0 = __expf(fmaf(s4[i][j][2*h],   scale, -newm));
                    float e1 = __expf(fmaf(s4[i][j][2*h+1], scale, -newm));
                    ps += e0 + e1;
                    s4[i][j][2*h]   = e0;
                    s4[i][j][2*h+1] = e1;
                }
                ps += __shfl_xor_sync(0xffffffffu, ps, 1);
                ps += __shfl_xor_sync(0xffffffffu, ps, 2);
                l_[i][h] = l_[i][h] * cv + ps;
#pragma unroll
                for (int j = 0; j < 8; j++) {
                    o[i][j][2*h]   *= cv;
                    o[i][j][2*h+1] *= cv;
                }
            }
            int rr = w * 32 + i * 16 + lg;
#pragma unroll
            for (int j = 0; j < 8; j++) {
                *(__half2*)(Ps_h + rr * 72 + j * 8 + 2 * lt) =
                    __floats2half2_rn(s4[i][j][0], s4[i][j][1]);
                *(__half2*)(Ps_h + (rr + 8) * 72 + j * 8 + 2 * lt) =
                    __floats2half2_rn(s4[i][j][2], s4[i][j][3]);
            }
        }

        if (kt + 1 < NT) { CPWAIT(1); } else { CPWAIT(0); }   // V[kt] done
        __syncthreads();            // V + Ps visible

        // O += P V  (V B-frags via ldmatrix.trans on [k][dv] tile)
#pragma unroll
        for (int ks = 0; ks < 4; ks++) {
            uint32_t af[2][4];
#pragma unroll
            for (int i = 0; i < 2; i++) {
                const uint32_t pa = sP +
                    (uint32_t)(((w * 32 + i * 16 + lr) * 72 + ks * 16 + lc) * 2);
                LDSM4(af[i][0], af[i][1], af[i][2], af[i][3], pa);
            }
#pragma unroll
            for (int g = 0; g < 4; g++) {
                uint32_t r0, r1, r2, r3;
                const uint32_t va = sV +
                    (uint32_t)(((ks * 16 + lr) * 72 + g * 16 + lc) * 2);
                LDSM4T(r0, r1, r2, r3, va);
                uint32_t bf0[2] = { r0, r1 };   // dv-group 2g
                uint32_t bf1[2] = { r2, r3 };   // dv-group 2g+1
#pragma unroll
                for (int i = 0; i < 2; i++) {
                    mma16(o[i][2*g],   af[i], bf0);
                    mma16(o[i][2*g+1], af[i], bf1);
                }
            }
        }
        __syncthreads();            // PV done; V buffer free
        if (kt + 1 < NT) issueV(kt + 1);
    }

    // final: divide by l, write fp16 Y (consumed by final GEMM)
#pragma unroll
    for (int i = 0; i < 2; i++) {
        float i0 = 1.0f / l_[i][0];
        float i1 = 1.0f / l_[i][1];
        int r0 = n0 + w * 32 + i * 16 + lg;
#pragma unroll
        for (int j = 0; j < 8; j++) {
            int cc = j * 8 + 2 * lt;
            *(__half2*)(Y + base + (size_t)r0 * DIM + cc) =
                __floats2half2_rn(o[i][j][0] * i0, o[i][j][1] * i0);
            *(__half2*)(Y + base + (size_t)(r0 + 8) * DIM + cc) =
                __floats2half2_rn(o[i][j][2] * i1, o[i][j][3] * i1);
        }
    }
}

// ---------------------------------------------------------------------------
// Inputs: kv, q, Wk, bk, Wq, bq, Wv, bv, Wp, bp
// ---------------------------------------------------------------------------
extern "C" void kernel_launch(void* const* d_in, const int* in_sizes, int n_in,
                              void* d_out, int out_size)
{
    const float* kv = (const float*)d_in[0];
    const float* q  = (const float*)d_in[1];
    const float* Wk = (const float*)d_in[2];
    const float* bk = (const float*)d_in[3];
    const float* Wq = (const float*)d_in[4];
    const float* bq = (const float*)d_in[5];
    const float* Wv = (const float*)d_in[6];
    const float* bv = (const float*)d_in[7];
    const float* Wp = (const float*)d_in[8];
    const float* bp = (const float*)d_in[9];
    float* out = (float*)d_out;

    __half *pK, *pQ, *pV, *pY, *pWt, *pkvh, *pqh;
    cudaGetSymbolAddress((void**)&pK, g_Kh);
    cudaGetSymbolAddress((void**)&pQ, g_Qh);
    cudaGetSymbolAddress((void**)&pV, g_Vh);
    cudaGetSymbolAddress((void**)&pY, g_Yh);
    cudaGetSymbolAddress((void**)&pWt, g_Wth);
    cudaGetSymbolAddress((void**)&pkvh, g_kvh);
    cudaGetSymbolAddress((void**)&pqh, g_qh);
    __half* Wtp = pWt + (size_t)3 * 1024 * 1024;

    const int GEMM_SMEM = 4 * GSMH * 2;   // 40960 B
    const int ATTN_SMEM = 27648 * 2;      // 55296 B
    cudaFuncSetAttribute((const void*)gemm3_kernel,
                         cudaFuncAttributeMaxDynamicSharedMemorySize, GEMM_SMEM);
    cudaFuncSetAttribute((const void*)gemmP_kernel,
                         cudaFuncAttributeMaxDynamicSharedMemorySize, GEMM_SMEM);
    cudaFuncSetAttribute((const void*)attn_mma_kernel,
                         cudaFuncAttributeMaxDynamicSharedMemorySize, ATTN_SMEM);

    dim3 tb(32, 8), tg(32, 32, 4);
    transpose4_kernel<<<tg, tb>>>(Wk, Wq, Wv, Wp, pWt);
    dim3 cg(2048, 1, 2);
    cvt_fp16_kernel<<<cg, 256>>>(kv, q, pkvh, pqh);

    dim3 g3(DIM / 128, RTOT / 128, 3);   // 768 CTAs
    gemm3_kernel<<<g3, 128, GEMM_SMEM>>>(pkvh, pqh, pWt, bk, bq, bv, pK, pQ, pV);

    dim3 ga(SEQ / 128, NHEAD, 2);        // 512 CTAs
    attn_mma_kernel<<<ga, 128, ATTN_SMEM>>>(pQ, pK, pV, pY);

    dim3 gg(DIM / 128, RTOT / 128);      // 256 CTAs
    gemmP_kernel<<<gg, 128, GEMM_SMEM>>>(pY, Wtp, bp, out);
}